// round 3
// baseline (speedup 1.0000x reference)
#include <cuda_runtime.h>
#include <math.h>

#define NMAX 110592
#define EMAX (NMAX*8)
#define PTOT 512

static __device__ __align__(16) float g_X  [NMAX*32];
static __device__ __align__(16) float g_AGG[NMAX*64];
static __device__ __align__(16) float g_H1 [NMAX*64];
static __device__ __align__(16) float g_H2 [NMAX*64];
static __device__ __align__(16) float g_EMB[NMAX*64];
static __device__ int   g_deg[NMAX];
static __device__ int   g_ptr[NMAX+1];
static __device__ int   g_cur[NMAX];
static __device__ int   g_adj[EMAX];
static __device__ int   g_offs[PTOT];
static __device__ int   g_offt[PTOT];
static __device__ __align__(16) float g_virt[64];

// ---------- exclusive scans of len_s, len_t (512 threads, 1 block) ----------
__global__ void k_offsets(const int* __restrict__ ls, const int* __restrict__ lt) {
    __shared__ int ws[16];
    int t = threadIdx.x, lane = t & 31, w = t >> 5;
    {
        int a = ls[t], v = a;
        #pragma unroll
        for (int d = 1; d < 32; d <<= 1) { int u = __shfl_up_sync(0xffffffffu, v, d); if (lane >= d) v += u; }
        if (lane == 31) ws[w] = v;
        __syncthreads();
        if (w == 0 && lane < 16) {
            int x = ws[lane];
            #pragma unroll
            for (int d = 1; d < 16; d <<= 1) { int u = __shfl_up_sync(0x0000ffffu, x, d); if (lane >= d) x += u; }
            ws[lane] = x;
        }
        __syncthreads();
        g_offs[t] = v - a + (w > 0 ? ws[w-1] : 0);
        __syncthreads();
    }
    {
        int a = lt[t], v = a;
        #pragma unroll
        for (int d = 1; d < 32; d <<= 1) { int u = __shfl_up_sync(0xffffffffu, v, d); if (lane >= d) v += u; }
        if (lane == 31) ws[w] = v;
        __syncthreads();
        if (w == 0 && lane < 16) {
            int x = ws[lane];
            #pragma unroll
            for (int d = 1; d < 16; d <<= 1) { int u = __shfl_up_sync(0x0000ffffu, x, d); if (lane >= d) x += u; }
            ws[lane] = x;
        }
        __syncthreads();
        g_offt[t] = v - a + (w > 0 ? ws[w-1] : 0);
    }
}

__global__ void k_copyX(const float* __restrict__ xs, const float* __restrict__ xt,
                        int nS32, int nTot32) {
    int i = blockIdx.x * blockDim.x + threadIdx.x;
    if (i < nTot32) g_X[i] = (i < nS32) ? xs[i] : xt[i - nS32];
}

__global__ void k_zero(int Ntot) {
    int i = blockIdx.x * blockDim.x + threadIdx.x;
    if (i < Ntot) g_deg[i] = 0;
}

__global__ void k_count(const int* __restrict__ ei, int E, int base) {
    int e = blockIdx.x * blockDim.x + threadIdx.x;
    if (e < E) atomicAdd(&g_deg[ei[E + e] + base], 1);
}

__global__ void k_scan(int Ntot) {
    __shared__ int ws[32];
    __shared__ int s_carry;
    int t = threadIdx.x, lane = t & 31, w = t >> 5;
    if (t == 0) s_carry = 0;
    __syncthreads();
    for (int base = 0; base < Ntot; base += 1024) {
        int i = base + t;
        int a = (i < Ntot) ? g_deg[i] : 0;
        int v = a;
        #pragma unroll
        for (int d = 1; d < 32; d <<= 1) { int u = __shfl_up_sync(0xffffffffu, v, d); if (lane >= d) v += u; }
        if (lane == 31) ws[w] = v;
        __syncthreads();
        if (w == 0) {
            int x = ws[lane];
            #pragma unroll
            for (int d = 1; d < 32; d <<= 1) { int u = __shfl_up_sync(0xffffffffu, x, d); if (lane >= d) x += u; }
            ws[lane] = x;
        }
        __syncthreads();
        int excl = v - a + (w > 0 ? ws[w-1] : 0) + s_carry;
        if (i < Ntot) { g_ptr[i] = excl; g_cur[i] = excl; }
        int btot = ws[31];
        __syncthreads();
        if (t == 0) s_carry += btot;
        __syncthreads();
    }
    if (t == 0) g_ptr[Ntot] = s_carry;
}

__global__ void k_fill(const int* __restrict__ ei, int E, int base) {
    int e = blockIdx.x * blockDim.x + threadIdx.x;
    if (e < E) {
        int src = ei[e], dst = ei[E + e];
        int pos = atomicAdd(&g_cur[dst + base], 1);
        g_adj[pos] = src + base;
    }
}

// sort each adjacency list -> deterministic float accumulation order
__global__ void k_sort(int Ntot) {
    int i = blockIdx.x * blockDim.x + threadIdx.x;
    if (i >= Ntot) return;
    int p0 = g_ptr[i], p1 = g_ptr[i + 1];
    for (int a = p0 + 1; a < p1; a++) {
        int key = g_adj[a]; int b = a - 1;
        while (b >= p0 && g_adj[b] > key) { g_adj[b + 1] = g_adj[b]; b--; }
        g_adj[b + 1] = key;
    }
}

__global__ void k_agg32(int Ntot) {
    int gw = (blockIdx.x * blockDim.x + threadIdx.x) >> 5;
    int lane = threadIdx.x & 31;
    if (gw >= Ntot) return;
    int p0 = g_ptr[gw], p1 = g_ptr[gw + 1];
    float a = 0.f;
    for (int e = p0; e < p1; e++) a += g_X[(size_t)g_adj[e] * 32 + lane];
    g_AGG[(size_t)gw * 32 + lane] = a;
}

__global__ void k_agg64(int Ntot) {
    int gw = (blockIdx.x * blockDim.x + threadIdx.x) >> 5;
    int lane = threadIdx.x & 31;
    if (gw >= Ntot) return;
    int p0 = g_ptr[gw], p1 = g_ptr[gw + 1];
    float a0 = 0.f, a1 = 0.f;
    for (int e = p0; e < p1; e++) {
        size_t r = (size_t)g_adj[e] * 64;
        a0 += g_H1[r + lane];
        a1 += g_H1[r + 32 + lane];
    }
    g_AGG[(size_t)gw * 64 + lane] = a0;
    g_AGG[(size_t)gw * 64 + 32 + lane] = a1;
}

// fused concat-GEMM, 64 nodes per block, 256 threads, 4x4 register tiles
// mode 0: A=[agg32|x]  K=64  -> H1 (relu);  mode 1: A=[agg64|h1] K=128 -> H2 (relu)
// mode 2: A=[x|h1|h2]  K=160 -> EMB (linear)
__global__ __launch_bounds__(256) void k_gemm(int mode,
        const float* __restrict__ W0, const float* __restrict__ W1, int split,
        const float* __restrict__ bias, int relu, int Ntot, int K) {
    extern __shared__ float sm[];
    float* As = sm;            // [K][68]
    float* Ws = sm + K * 68;   // [K][64]
    int node0 = blockIdx.x * 64, tid = threadIdx.x;

    for (int idx = tid; idx < 64 * K; idx += 256) {
        int nd = idx / K, k = idx - nd * K;
        int node = node0 + nd;
        float v = 0.f;
        if (node < Ntot) {
            size_t n64 = (size_t)node * 64, n32 = (size_t)node * 32;
            if (mode == 0)      v = (k < 32) ? g_AGG[n32 + k] : g_X[n32 + k - 32];
            else if (mode == 1) v = (k < 64) ? g_AGG[n64 + k] : g_H1[n64 + k - 64];
            else                v = (k < 32) ? g_X[n32 + k]
                                  : (k < 96) ? g_H1[n64 + k - 32]
                                             : g_H2[n64 + k - 96];
        }
        As[k * 68 + nd] = v;
    }
    for (int idx = tid; idx < K * 64; idx += 256) {
        int k = idx >> 6, f = idx & 63;
        Ws[idx] = (k < split) ? W0[k * 64 + f] : W1[(k - split) * 64 + f];
    }
    __syncthreads();

    int ti = tid >> 4, tj = tid & 15;
    float acc[4][4] = {{0,0,0,0},{0,0,0,0},{0,0,0,0},{0,0,0,0}};
    #pragma unroll 4
    for (int k = 0; k < K; k++) {
        float4 a = *(const float4*)&As[k * 68 + 4 * ti];
        float4 b = *(const float4*)&Ws[k * 64 + 4 * tj];
        acc[0][0] += a.x*b.x; acc[0][1] += a.x*b.y; acc[0][2] += a.x*b.z; acc[0][3] += a.x*b.w;
        acc[1][0] += a.y*b.x; acc[1][1] += a.y*b.y; acc[1][2] += a.y*b.z; acc[1][3] += a.y*b.w;
        acc[2][0] += a.z*b.x; acc[2][1] += a.z*b.y; acc[2][2] += a.z*b.z; acc[2][3] += a.z*b.w;
        acc[3][0] += a.w*b.x; acc[3][1] += a.w*b.y; acc[3][2] += a.w*b.z; acc[3][3] += a.w*b.w;
    }
    float4 bb = *(const float4*)&bias[4 * tj];
    float* outp = (mode == 0) ? g_H1 : (mode == 1) ? g_H2 : g_EMB;
    #pragma unroll
    for (int r = 0; r < 4; r++) {
        int node = node0 + 4 * ti + r;
        if (node < Ntot) {
            float4 o;
            o.x = acc[r][0] + bb.x; o.y = acc[r][1] + bb.y;
            o.z = acc[r][2] + bb.z; o.w = acc[r][3] + bb.w;
            if (relu) {
                o.x = fmaxf(o.x, 0.f); o.y = fmaxf(o.y, 0.f);
                o.z = fmaxf(o.z, 0.f); o.w = fmaxf(o.w, 0.f);
            }
            *(float4*)&outp[(size_t)node * 64 + 4 * tj] = o;
        }
    }
}

__global__ void k_norm(int Ntot) {
    int gw = (blockIdx.x * blockDim.x + threadIdx.x) >> 5;
    int lane = threadIdx.x & 31;
    if (gw >= Ntot) return;
    size_t r = (size_t)gw * 64;
    float a = g_EMB[r + lane], b = g_EMB[r + 32 + lane];
    float s = a * a + b * b;
    #pragma unroll
    for (int d = 16; d; d >>= 1) s += __shfl_xor_sync(0xffffffffu, s, d);
    float inv = 1.0f / fmaxf(sqrtf(s), 1e-12f);
    g_EMB[r + lane] = a * inv;
    g_EMB[r + 32 + lane] = b * inv;
}

__global__ void k_norm_virt(const float* __restrict__ virt) {
    __shared__ float red[64];
    int t = threadIdx.x;
    float v = virt[t];
    red[t] = v * v;
    __syncthreads();
    #pragma unroll
    for (int s = 32; s; s >>= 1) { if (t < s) red[t] += red[t + s]; __syncthreads(); }
    g_virt[t] = v / fmaxf(sqrtf(red[0]), 1e-12f);
}

// ---------------- per-pair: cost + K + Sinkhorn + gamma + geds ----------------
__global__ __launch_bounds__(256) void k_pair(const int* __restrict__ ls, const int* __restrict__ lt,
        int Ns, float* __restrict__ gamma, float* __restrict__ cost, float* __restrict__ geds2) {
    extern __shared__ float sm[];
    float* Km   = sm;               // [192][192]
    float* Ssub = sm + 36864;       // [64][68]
    float* Tsub = Ssub + 4352;      // [64][68]
    float* sqs  = Tsub + 4352;      // [192]
    float* sqt  = sqs + 192;        // [192]
    float* uu   = sqt + 192;        // [192]
    float* vv   = uu + 192;         // [192]
    float* red  = vv + 192;         // [256]

    int p = blockIdx.x, tid = threadIdx.x;
    int n = ls[p], m = lt[p], q = 192 - n;
    int offs = g_offs[p], offt = g_offt[p];
    const float* EB = g_EMB;

    for (int i = tid; i < n; i += 256) {
        const float4* r = (const float4*)(EB + (size_t)(offs + i) * 64);
        float s = 0.f;
        #pragma unroll
        for (int k = 0; k < 16; k++) { float4 x = r[k]; s += x.x*x.x + x.y*x.y + x.z*x.z + x.w*x.w; }
        sqs[i] = s;
    }
    for (int j = tid; j < n; j += 256) {
        const float4* r = (j < m) ? (const float4*)(EB + (size_t)(Ns + offt + j) * 64)
                                  : (const float4*)g_virt;
        float s = 0.f;
        #pragma unroll
        for (int k = 0; k < 16; k++) { float4 x = r[k]; s += x.x*x.x + x.y*x.y + x.z*x.z + x.w*x.w; }
        sqt[j] = s;
    }
    for (int i = tid; i < 192; i += 256) {
        uu[i] = 1.0f / 192.0f;
        vv[i] = (i >= n && q > 0) ? (192.0f / (float)q) : 0.f;  // pad v is stationary
    }
    __syncthreads();

    float* costp = cost + (size_t)p * 36864;
    float* gamp  = gamma + (size_t)p * 36864;

    int ti = tid >> 4, tj = tid & 15;
    for (int i0 = 0; i0 < 192; i0 += 64) {
        for (int j0 = 0; j0 < 192; j0 += 64) {
            if (i0 < n && j0 < n) {
                for (int idx = tid; idx < 4096; idx += 256) {
                    int nd = idx >> 6, k = idx & 63;
                    int i = i0 + nd; if (i >= n) i = n - 1;
                    Ssub[k * 68 + nd] = EB[(size_t)(offs + i) * 64 + k];
                }
                for (int idx = tid; idx < 4096; idx += 256) {
                    int nd = idx >> 6, k = idx & 63;
                    int j = j0 + nd;
                    const float* r = (j < m) ? (EB + (size_t)(Ns + offt + j) * 64) : g_virt;
                    Tsub[k * 68 + nd] = r[k];
                }
                __syncthreads();
                float acc[4][4] = {{0,0,0,0},{0,0,0,0},{0,0,0,0},{0,0,0,0}};
                #pragma unroll 4
                for (int k = 0; k < 64; k++) {
                    float4 a = *(const float4*)&Ssub[k * 68 + 4 * ti];
                    float4 b = *(const float4*)&Tsub[k * 68 + 4 * tj];
                    acc[0][0] += a.x*b.x; acc[0][1] += a.x*b.y; acc[0][2] += a.x*b.z; acc[0][3] += a.x*b.w;
                    acc[1][0] += a.y*b.x; acc[1][1] += a.y*b.y; acc[1][2] += a.y*b.z; acc[1][3] += a.y*b.w;
                    acc[2][0] += a.z*b.x; acc[2][1] += a.z*b.y; acc[2][2] += a.z*b.z; acc[2][3] += a.z*b.w;
                    acc[3][0] += a.w*b.x; acc[3][1] += a.w*b.y; acc[3][2] += a.w*b.z; acc[3][3] += a.w*b.w;
                }
                #pragma unroll
                for (int r = 0; r < 4; r++) {
                    int i = i0 + 4 * ti + r;
                    float cv[4], kv[4];
                    #pragma unroll
                    for (int c = 0; c < 4; c++) {
                        int j = j0 + 4 * tj + c;
                        if (i < n && j < n) {
                            float d = sqs[i] + sqt[j] - 2.0f * acc[r][c];
                            float cd = sqrtf(fmaxf(d, 1e-12f));
                            cv[c] = cd;
                            kv[c] = __expf(-10.0f * cd);
                        } else {
                            bool pad = (i >= n) && (j >= n);
                            cv[c] = pad ? 0.f : 1000.f;
                            kv[c] = pad ? 1.f : 0.f;
                        }
                    }
                    *(float4*)&costp[i * 192 + j0 + 4 * tj] = make_float4(cv[0], cv[1], cv[2], cv[3]);
                    *(float4*)&Km[i * 192 + j0 + 4 * tj]    = make_float4(kv[0], kv[1], kv[2], kv[3]);
                }
                __syncthreads();
            } else {
                #pragma unroll
                for (int r = 0; r < 4; r++) {
                    int i = i0 + 4 * ti + r;
                    float cv[4], kv[4];
                    #pragma unroll
                    for (int c = 0; c < 4; c++) {
                        int j = j0 + 4 * tj + c;
                        bool pad = (i >= n) && (j >= n);
                        cv[c] = pad ? 0.f : 1000.f;
                        kv[c] = pad ? 1.f : 0.f;
                    }
                    *(float4*)&costp[i * 192 + j0 + 4 * tj] = make_float4(cv[0], cv[1], cv[2], cv[3]);
                    *(float4*)&Km[i * 192 + j0 + 4 * tj]    = make_float4(kv[0], kv[1], kv[2], kv[3]);
                }
            }
        }
    }
    __syncthreads();

    // Sinkhorn: only the n x n real block needs iteration (cross K = 0 exactly,
    // pad u = 1/192 and pad v = 192/q are stationary).
    int w = tid >> 5, lane = tid & 31;
    for (int it = 0; it < 8; it++) {
        for (int j = tid; j < n; j += 256) {
            float s = 0.f;
            for (int i = 0; i < n; i++) s += Km[i * 192 + j] * uu[i];
            vv[j] = 1.0f / s;
        }
        __syncthreads();
        for (int i = w; i < n; i += 8) {
            float s = 0.f;
            for (int j = lane; j < n; j += 32) s += Km[i * 192 + j] * vv[j];
            #pragma unroll
            for (int d = 16; d; d >>= 1) s += __shfl_xor_sync(0xffffffffu, s, d);
            if (lane == 0) uu[i] = 1.0f / s;
        }
        __syncthreads();
    }

    // gamma = u K v, geds = sum(gamma * cost)
    float loc = 0.f;
    for (int idx = tid; idx < 9216; idx += 256) {
        int i = idx / 48, jb = (idx - i * 48) * 4;
        float4 k4 = *(const float4*)&Km[i * 192 + jb];
        float4 c4 = *(const float4*)&costp[i * 192 + jb];
        float ui = uu[i];
        float4 g;
        g.x = ui * k4.x * vv[jb];
        g.y = ui * k4.y * vv[jb + 1];
        g.z = ui * k4.z * vv[jb + 2];
        g.w = ui * k4.w * vv[jb + 3];
        *(float4*)&gamp[i * 192 + jb] = g;
        loc += g.x * c4.x + g.y * c4.y + g.z * c4.z + g.w * c4.w;
    }
    red[tid] = loc;
    __syncthreads();
    #pragma unroll
    for (int s = 128; s; s >>= 1) { if (tid < s) red[tid] += red[tid + s]; __syncthreads(); }
    if (tid == 0) geds2[p] = red[0] / (float)(n + m);
}

extern "C" void kernel_launch(void* const* d_in, const int* in_sizes, int n_in,
                              void* d_out, int out_size) {
    const float* x_s     = (const float*)d_in[0];
    const float* x_t     = (const float*)d_in[1];
    const float* W_rel0  = (const float*)d_in[2];
    const float* b_rel0  = (const float*)d_in[3];
    const float* W_root0 = (const float*)d_in[4];
    const float* W_rel1  = (const float*)d_in[5];
    const float* b_rel1  = (const float*)d_in[6];
    const float* W_root1 = (const float*)d_in[7];
    const float* W_e     = (const float*)d_in[8];
    const float* b_e     = (const float*)d_in[9];
    const float* virt    = (const float*)d_in[10];
    const int* ei_s      = (const int*)d_in[11];
    const int* ei_t      = (const int*)d_in[12];
    const int* len_s     = (const int*)d_in[13];
    const int* len_t     = (const int*)d_in[14];

    int Ns = in_sizes[0] / 32, Nt = in_sizes[1] / 32;
    int Es = in_sizes[11] / 2, Et = in_sizes[12] / 2;
    int Ntot = Ns + Nt;

    float* out   = (float*)d_out;
    float* gamma = out;
    float* cost  = out + (size_t)PTOT * 36864;
    float* geds2 = cost + (size_t)PTOT * 36864;

    cudaFuncSetAttribute(k_gemm, cudaFuncAttributeMaxDynamicSharedMemorySize, 160 * 132 * 4);
    cudaFuncSetAttribute(k_pair, cudaFuncAttributeMaxDynamicSharedMemorySize, 46592 * 4);

    k_offsets<<<1, 512>>>(len_s, len_t);
    k_copyX<<<(Ntot * 32 + 255) / 256, 256>>>(x_s, x_t, Ns * 32, Ntot * 32);
    k_zero<<<(Ntot + 255) / 256, 256>>>(Ntot);
    k_count<<<(Es + 255) / 256, 256>>>(ei_s, Es, 0);
    k_count<<<(Et + 255) / 256, 256>>>(ei_t, Et, Ns);
    k_scan<<<1, 1024>>>(Ntot);
    k_fill<<<(Es + 255) / 256, 256>>>(ei_s, Es, 0);
    k_fill<<<(Et + 255) / 256, 256>>>(ei_t, Et, Ns);
    k_sort<<<(Ntot + 255) / 256, 256>>>(Ntot);

    int gw = (Ntot + 7) / 8;   // warp-per-node grids
    int gb = (Ntot + 63) / 64; // 64-node gemm grids
    k_agg32<<<gw, 256>>>(Ntot);
    k_gemm<<<gb, 256, 64 * 132 * 4>>>(0, W_rel0, W_root0, 32, b_rel0, 1, Ntot, 64);
    k_agg64<<<gw, 256>>>(Ntot);
    k_gemm<<<gb, 256, 128 * 132 * 4>>>(1, W_rel1, W_root1, 64, b_rel1, 1, Ntot, 128);
    k_gemm<<<gb, 256, 160 * 132 * 4>>>(2, W_e, W_e, 160, b_e, 0, Ntot, 160);
    k_norm<<<gw, 256>>>(Ntot);
    k_norm_virt<<<1, 64>>>(virt);

    k_pair<<<PTOT, 256, 46592 * 4>>>(len_s, len_t, Ns, gamma, cost, geds2);
}

// round 4
// speedup vs baseline: 1.0610x; 1.0610x over previous
#include <cuda_runtime.h>
#include <math.h>

#define NMAX 110592
#define EMAX (NMAX*8)
#define PTOT 512

static __device__ __align__(16) float g_X  [NMAX*32];
static __device__ __align__(16) float g_H1 [NMAX*64];
static __device__ __align__(16) float g_H2 [NMAX*64];
static __device__ __align__(16) float g_EMB[NMAX*64];
static __device__ int   g_deg[NMAX];
static __device__ int   g_ptr[NMAX+1];
static __device__ int   g_cur[NMAX];
static __device__ int   g_adj[EMAX];
static __device__ int   g_bsum[128];
static __device__ int   g_boff[128];
static __device__ int   g_offs[PTOT];
static __device__ int   g_offt[PTOT];
static __device__ int   g_order[PTOT];
static __device__ __align__(16) float g_virt[64];

// ---------------- setup: copy X, zero deg, offsets, pair order, virt norm ----------------
__global__ void k_setup(const float* __restrict__ xs, const float* __restrict__ xt,
                        int nS32, int nTot32, int Ntot,
                        const int* __restrict__ ls, const int* __restrict__ lt,
                        const float* __restrict__ virt) {
    int gid = blockIdx.x * 256 + threadIdx.x;
    if (gid < nTot32) g_X[gid] = (gid < nS32) ? xs[gid] : xt[gid - nS32];
    if (gid < Ntot) g_deg[gid] = 0;
    if (blockIdx.x == 0) {
        int tid = threadIdx.x;
        for (int t = tid; t < PTOT; t += 256) {
            int accs = 0, acct = 0;
            for (int p = 0; p < PTOT; p++) {
                int c = (p < t);
                accs += c ? ls[p] : 0;
                acct += c ? lt[p] : 0;
            }
            g_offs[t] = accs;
            g_offt[t] = acct;
            // rank in descending len_s order (stable)
            int n_t = ls[t], rank = 0;
            for (int p = 0; p < PTOT; p++) {
                int np = ls[p];
                rank += (np > n_t) || (np == n_t && p < t);
            }
            g_order[rank] = t;
        }
        if (tid < 64) {
            float s = 0.f;
            for (int j = 0; j < 64; j++) { float v = virt[j]; s += v * v; }
            g_virt[tid] = virt[tid] * rsqrtf(fmaxf(s, 1e-24f));
        }
    }
}

__global__ void k_count_all(const int* __restrict__ eis, int Es,
                            const int* __restrict__ eit, int Et, int Ns) {
    int e = blockIdx.x * 256 + threadIdx.x;
    if (e < Es) atomicAdd(&g_deg[eis[Es + e]], 1);
    else if (e < Es + Et) atomicAdd(&g_deg[eit[Et + (e - Es)] + Ns], 1);
}

// ---------------- hierarchical scan ----------------
__global__ void k_scanA(int Ntot) {
    __shared__ int ws[32];
    int t = threadIdx.x, lane = t & 31, w = t >> 5;
    int i = blockIdx.x * 1024 + t;
    int a = (i < Ntot) ? g_deg[i] : 0;
    int v = a;
    #pragma unroll
    for (int d = 1; d < 32; d <<= 1) { int u = __shfl_up_sync(0xffffffffu, v, d); if (lane >= d) v += u; }
    if (lane == 31) ws[w] = v;
    __syncthreads();
    if (w == 0) {
        int x = ws[lane];
        #pragma unroll
        for (int d = 1; d < 32; d <<= 1) { int u = __shfl_up_sync(0xffffffffu, x, d); if (lane >= d) x += u; }
        ws[lane] = x;
    }
    __syncthreads();
    int excl = v - a + (w > 0 ? ws[w - 1] : 0);
    if (i < Ntot) g_ptr[i] = excl;
    if (t == 1023) g_bsum[blockIdx.x] = excl + a;
}

__global__ void k_scanB(int nb, int Ntot) {
    __shared__ int sm2[128];
    int t = threadIdx.x;
    int a = (t < nb) ? g_bsum[t] : 0;
    sm2[t] = a;
    __syncthreads();
    #pragma unroll
    for (int d = 1; d < 128; d <<= 1) {
        int x = (t >= d) ? sm2[t - d] : 0;
        __syncthreads();
        sm2[t] += x;
        __syncthreads();
    }
    if (t < nb) g_boff[t] = sm2[t] - a;
    if (t == nb - 1) g_ptr[Ntot] = sm2[t];
}

__global__ void k_scanC(int Ntot) {
    int i = blockIdx.x * 256 + threadIdx.x;
    if (i < Ntot) {
        int v = g_ptr[i] + g_boff[i >> 10];
        g_ptr[i] = v;
        g_cur[i] = v;
    }
}

__global__ void k_fill_all(const int* __restrict__ eis, int Es,
                           const int* __restrict__ eit, int Et, int Ns) {
    int e = blockIdx.x * 256 + threadIdx.x;
    if (e < Es) {
        int pos = atomicAdd(&g_cur[eis[Es + e]], 1);
        g_adj[pos] = eis[e];
    } else if (e < Es + Et) {
        int i = e - Es;
        int pos = atomicAdd(&g_cur[eit[Et + i] + Ns], 1);
        g_adj[pos] = eit[i] + Ns;
    }
}

// deterministic accumulation order
__global__ void k_sort(int Ntot) {
    int i = blockIdx.x * 256 + threadIdx.x;
    if (i >= Ntot) return;
    int p0 = g_ptr[i], p1 = g_ptr[i + 1];
    for (int a = p0 + 1; a < p1; a++) {
        int key = g_adj[a]; int b = a - 1;
        while (b >= p0 && g_adj[b] > key) { g_adj[b + 1] = g_adj[b]; b--; }
        g_adj[b + 1] = key;
    }
}

// ---------------- fused gather + concat-GEMM ----------------
// MODE 0: A=[agg(X)|X]   K=64  -> H1 (relu)
// MODE 1: A=[agg(H1)|H1] K=128 -> H2 (relu)
// MODE 2: A=[X|H1|H2]    K=160 -> EMB (normalized rows)
template <int MODE, int K>
__global__ __launch_bounds__(256) void k_gemm(
        const float* __restrict__ W0, const float* __restrict__ W1, int split,
        const float* __restrict__ bias, int Ntot) {
    extern __shared__ float sm[];
    float* As = sm;            // [K][68]
    float* Ws = sm + K * 68;   // [K][64]
    int node0 = blockIdx.x * 64, tid = threadIdx.x;

    for (int idx = tid; idx < 64 * K; idx += 256) {
        int nd = idx / K, k = idx - nd * K;
        int node = node0 + nd;
        float v = 0.f;
        if (node < Ntot) {
            size_t n64 = (size_t)node * 64, n32 = (size_t)node * 32;
            if (MODE == 0) {
                if (k < 32) {
                    int p0 = g_ptr[node], p1 = g_ptr[node + 1];
                    for (int e = p0; e < p1; e++) v += g_X[(size_t)g_adj[e] * 32 + k];
                } else v = g_X[n32 + k - 32];
            } else if (MODE == 1) {
                if (k < 64) {
                    int p0 = g_ptr[node], p1 = g_ptr[node + 1];
                    for (int e = p0; e < p1; e++) v += g_H1[(size_t)g_adj[e] * 64 + k];
                } else v = g_H1[n64 + k - 64];
            } else {
                v = (k < 32) ? g_X[n32 + k]
                  : (k < 96) ? g_H1[n64 + k - 32]
                             : g_H2[n64 + k - 96];
            }
        }
        As[k * 68 + nd] = v;
    }
    for (int idx = tid; idx < K * 64; idx += 256) {
        int k = idx >> 6, f = idx & 63;
        Ws[idx] = (k < split) ? W0[k * 64 + f] : W1[(k - split) * 64 + f];
    }
    __syncthreads();

    int ti = tid >> 4, tj = tid & 15;
    float acc[4][4] = {{0,0,0,0},{0,0,0,0},{0,0,0,0},{0,0,0,0}};
    #pragma unroll 4
    for (int k = 0; k < K; k++) {
        float4 a = *(const float4*)&As[k * 68 + 4 * ti];
        float4 b = *(const float4*)&Ws[k * 64 + 4 * tj];
        acc[0][0] += a.x*b.x; acc[0][1] += a.x*b.y; acc[0][2] += a.x*b.z; acc[0][3] += a.x*b.w;
        acc[1][0] += a.y*b.x; acc[1][1] += a.y*b.y; acc[1][2] += a.y*b.z; acc[1][3] += a.y*b.w;
        acc[2][0] += a.z*b.x; acc[2][1] += a.z*b.y; acc[2][2] += a.z*b.z; acc[2][3] += a.z*b.w;
        acc[3][0] += a.w*b.x; acc[3][1] += a.w*b.y; acc[3][2] += a.w*b.z; acc[3][3] += a.w*b.w;
    }
    float4 bb = *(const float4*)&bias[4 * tj];
    float* outp = (MODE == 0) ? g_H1 : (MODE == 1) ? g_H2 : g_EMB;
    #pragma unroll
    for (int r = 0; r < 4; r++) {
        int node = node0 + 4 * ti + r;
        float4 o;
        o.x = acc[r][0] + bb.x; o.y = acc[r][1] + bb.y;
        o.z = acc[r][2] + bb.z; o.w = acc[r][3] + bb.w;
        if (MODE < 2) {
            o.x = fmaxf(o.x, 0.f); o.y = fmaxf(o.y, 0.f);
            o.z = fmaxf(o.z, 0.f); o.w = fmaxf(o.w, 0.f);
        } else {
            // row normalize: reduce sum of squares across the 16 tj lanes
            float ss = o.x*o.x + o.y*o.y + o.z*o.z + o.w*o.w;
            #pragma unroll
            for (int d = 1; d < 16; d <<= 1) ss += __shfl_xor_sync(0xffffffffu, ss, d);
            float inv = rsqrtf(fmaxf(ss, 1e-24f));
            o.x *= inv; o.y *= inv; o.z *= inv; o.w *= inv;
        }
        if (node < Ntot) *(float4*)&outp[(size_t)node * 64 + 4 * tj] = o;
    }
}

// ---------------- per-pair: cost/K + Sinkhorn + gamma/cost/geds ----------------
__global__ __launch_bounds__(256) void k_pair(const int* __restrict__ ls, const int* __restrict__ lt,
        int Ns, float* __restrict__ gamma, float* __restrict__ cost, float* __restrict__ geds2) {
    extern __shared__ float sm[];
    float* Km   = sm;               // [192][192]
    float* Ssub = sm + 36864;       // [64][68]
    float* Tsub = Ssub + 4352;      // [64][68]
    float* sqs  = Tsub + 4352;      // [192]
    float* sqt  = sqs + 192;        // [192]
    float* uu   = sqt + 192;        // [192]
    float* vv   = uu + 192;         // [192]
    float* red  = vv + 192;         // [256]

    int p = g_order[blockIdx.x];
    int tid = threadIdx.x;
    int n = ls[p], m = lt[p], q = 192 - n;
    int offs = g_offs[p], offt = g_offt[p];
    const float* EB = g_EMB;

    for (int i = tid; i < n; i += 256) {
        const float4* r = (const float4*)(EB + (size_t)(offs + i) * 64);
        float s = 0.f;
        #pragma unroll
        for (int k = 0; k < 16; k++) { float4 x = r[k]; s += x.x*x.x + x.y*x.y + x.z*x.z + x.w*x.w; }
        sqs[i] = s;
    }
    for (int j = tid; j < n; j += 256) {
        const float4* r = (j < m) ? (const float4*)(EB + (size_t)(Ns + offt + j) * 64)
                                  : (const float4*)g_virt;
        float s = 0.f;
        #pragma unroll
        for (int k = 0; k < 16; k++) { float4 x = r[k]; s += x.x*x.x + x.y*x.y + x.z*x.z + x.w*x.w; }
        sqt[j] = s;
    }
    for (int i = tid; i < 192; i += 256) {
        uu[i] = 1.0f / 192.0f;
        vv[i] = (i >= n && q > 0) ? (192.0f / (float)q) : 0.f;  // pad v stationary
    }

    int ti = tid >> 4, tj = tid & 15;
    for (int i0 = 0; i0 < 192; i0 += 64) {
        if (i0 < n) {
            __syncthreads();
            for (int idx = tid; idx < 4096; idx += 256) {
                int nd = idx >> 6, k = idx & 63;
                int i = i0 + nd; if (i >= n) i = n - 1;
                Ssub[k * 68 + nd] = EB[(size_t)(offs + i) * 64 + k];
            }
        }
        for (int j0 = 0; j0 < 192; j0 += 64) {
            if (i0 < n && j0 < n) {
                __syncthreads();
                for (int idx = tid; idx < 4096; idx += 256) {
                    int nd = idx >> 6, k = idx & 63;
                    int j = j0 + nd;
                    const float* r = (j < m) ? (EB + (size_t)(Ns + offt + j) * 64) : g_virt;
                    Tsub[k * 68 + nd] = r[k];
                }
                __syncthreads();
                float acc[4][4] = {{0,0,0,0},{0,0,0,0},{0,0,0,0},{0,0,0,0}};
                #pragma unroll 4
                for (int k = 0; k < 64; k++) {
                    float4 a = *(const float4*)&Ssub[k * 68 + 4 * ti];
                    float4 b = *(const float4*)&Tsub[k * 68 + 4 * tj];
                    acc[0][0] += a.x*b.x; acc[0][1] += a.x*b.y; acc[0][2] += a.x*b.z; acc[0][3] += a.x*b.w;
                    acc[1][0] += a.y*b.x; acc[1][1] += a.y*b.y; acc[1][2] += a.y*b.z; acc[1][3] += a.y*b.w;
                    acc[2][0] += a.z*b.x; acc[2][1] += a.z*b.y; acc[2][2] += a.z*b.z; acc[2][3] += a.z*b.w;
                    acc[3][0] += a.w*b.x; acc[3][1] += a.w*b.y; acc[3][2] += a.w*b.z; acc[3][3] += a.w*b.w;
                }
                #pragma unroll
                for (int r = 0; r < 4; r++) {
                    int i = i0 + 4 * ti + r;
                    float kv[4];
                    #pragma unroll
                    for (int c = 0; c < 4; c++) {
                        int j = j0 + 4 * tj + c;
                        if (i < n && j < n) {
                            float d = fmaxf(sqs[i] + sqt[j] - 2.0f * acc[r][c], 1e-12f);
                            float cd = d * rsqrtf(d);
                            kv[c] = __expf(-10.0f * cd);
                        } else {
                            kv[c] = ((i >= n) && (j >= n)) ? 1.f : 0.f;
                        }
                    }
                    *(float4*)&Km[i * 192 + j0 + 4 * tj] = make_float4(kv[0], kv[1], kv[2], kv[3]);
                }
            } else {
                #pragma unroll
                for (int r = 0; r < 4; r++) {
                    int i = i0 + 4 * ti + r;
                    float kv[4];
                    #pragma unroll
                    for (int c = 0; c < 4; c++) {
                        int j = j0 + 4 * tj + c;
                        kv[c] = ((i >= n) && (j >= n)) ? 1.f : 0.f;
                    }
                    *(float4*)&Km[i * 192 + j0 + 4 * tj] = make_float4(kv[0], kv[1], kv[2], kv[3]);
                }
            }
        }
    }
    __syncthreads();

    // Sinkhorn on the n x n real block (cross K = 0 exactly; pad u,v stationary)
    int w = tid >> 5, lane = tid & 31;
    for (int it = 0; it < 8; it++) {
        for (int j = tid; j < n; j += 256) {
            float s = 0.f;
            for (int i = 0; i < n; i++) s += Km[i * 192 + j] * uu[i];
            vv[j] = 1.0f / s;
        }
        __syncthreads();
        for (int i = w; i < n; i += 8) {
            float s = 0.f;
            for (int j = lane; j < n; j += 32) s += Km[i * 192 + j] * vv[j];
            #pragma unroll
            for (int d = 16; d; d >>= 1) s += __shfl_xor_sync(0xffffffffu, s, d);
            if (lane == 0) uu[i] = 1.0f / s;
        }
        __syncthreads();
    }

    // epilogue: gamma = u K v; cost recomputed (in-block: -0.1*ln K); geds
    float* costp = cost + (size_t)p * 36864;
    float* gamp  = gamma + (size_t)p * 36864;
    float loc = 0.f;
    for (int idx = tid; idx < 9216; idx += 256) {
        int i = idx / 48, jb = (idx - i * 48) * 4;
        float4 k4 = *(const float4*)&Km[i * 192 + jb];
        float ui = uu[i];
        float4 g, c4;
        float kk[4] = {k4.x, k4.y, k4.z, k4.w};
        float gg[4], cc[4];
        #pragma unroll
        for (int c = 0; c < 4; c++) {
            int j = jb + c;
            bool inb = (i < n) && (j < n);
            cc[c] = inb ? (-0.1f * __logf(kk[c]))
                        : (((i >= n) && (j >= n)) ? 0.f : 1000.f);
            gg[c] = ui * kk[c] * vv[j];
            loc += gg[c] * cc[c];
        }
        g = make_float4(gg[0], gg[1], gg[2], gg[3]);
        c4 = make_float4(cc[0], cc[1], cc[2], cc[3]);
        *(float4*)&gamp[i * 192 + jb] = g;
        *(float4*)&costp[i * 192 + jb] = c4;
    }
    red[tid] = loc;
    __syncthreads();
    #pragma unroll
    for (int s = 128; s; s >>= 1) { if (tid < s) red[tid] += red[tid + s]; __syncthreads(); }
    if (tid == 0) geds2[p] = red[0] / (float)(n + m);
}

extern "C" void kernel_launch(void* const* d_in, const int* in_sizes, int n_in,
                              void* d_out, int out_size) {
    const float* x_s     = (const float*)d_in[0];
    const float* x_t     = (const float*)d_in[1];
    const float* W_rel0  = (const float*)d_in[2];
    const float* b_rel0  = (const float*)d_in[3];
    const float* W_root0 = (const float*)d_in[4];
    const float* W_rel1  = (const float*)d_in[5];
    const float* b_rel1  = (const float*)d_in[6];
    const float* W_root1 = (const float*)d_in[7];
    const float* W_e     = (const float*)d_in[8];
    const float* b_e     = (const float*)d_in[9];
    const float* virt    = (const float*)d_in[10];
    const int* ei_s      = (const int*)d_in[11];
    const int* ei_t      = (const int*)d_in[12];
    const int* len_s     = (const int*)d_in[13];
    const int* len_t     = (const int*)d_in[14];

    int Ns = in_sizes[0] / 32, Nt = in_sizes[1] / 32;
    int Es = in_sizes[11] / 2, Et = in_sizes[12] / 2;
    int Ntot = Ns + Nt;
    int Etot = Es + Et;

    float* out   = (float*)d_out;
    float* gamma = out;
    float* cost  = out + (size_t)PTOT * 36864;
    float* geds2 = cost + (size_t)PTOT * 36864;

    cudaFuncSetAttribute(k_gemm<0,64>,  cudaFuncAttributeMaxDynamicSharedMemorySize, 64  * 132 * 4);
    cudaFuncSetAttribute(k_gemm<1,128>, cudaFuncAttributeMaxDynamicSharedMemorySize, 128 * 132 * 4);
    cudaFuncSetAttribute(k_gemm<2,160>, cudaFuncAttributeMaxDynamicSharedMemorySize, 160 * 132 * 4);
    cudaFuncSetAttribute(k_pair, cudaFuncAttributeMaxDynamicSharedMemorySize, 46592 * 4);

    int nb = (Ntot + 1023) / 1024;
    k_setup<<<(Ntot * 32 + 255) / 256, 256>>>(x_s, x_t, Ns * 32, Ntot * 32, Ntot, len_s, len_t, virt);
    k_count_all<<<(Etot + 255) / 256, 256>>>(ei_s, Es, ei_t, Et, Ns);
    k_scanA<<<nb, 1024>>>(Ntot);
    k_scanB<<<1, 128>>>(nb, Ntot);
    k_scanC<<<(Ntot + 255) / 256, 256>>>(Ntot);
    k_fill_all<<<(Etot + 255) / 256, 256>>>(ei_s, Es, ei_t, Et, Ns);
    k_sort<<<(Ntot + 255) / 256, 256>>>(Ntot);

    int gb = (Ntot + 63) / 64;
    k_gemm<0,64> <<<gb, 256, 64  * 132 * 4>>>(W_rel0, W_root0, 32, b_rel0, Ntot);
    k_gemm<1,128><<<gb, 256, 128 * 132 * 4>>>(W_rel1, W_root1, 64, b_rel1, Ntot);
    k_gemm<2,160><<<gb, 256, 160 * 132 * 4>>>(W_e, W_e, 160, b_e, Ntot);

    k_pair<<<PTOT, 256, 46592 * 4>>>(len_s, len_t, Ns, gamma, cost, geds2);
}

// round 5
// speedup vs baseline: 1.3783x; 1.2991x over previous
#include <cuda_runtime.h>
#include <math.h>

#define NMAX 110592
#define EMAX (NMAX*8)
#define PTOT 512

static __device__ __align__(16) float g_X  [NMAX*32];
static __device__ __align__(16) float g_H1 [NMAX*64];
static __device__ __align__(16) float g_H2 [NMAX*64];
static __device__ __align__(16) float g_EMB[NMAX*64];
static __device__ int   g_deg[NMAX];        // invariant: zero at kernel_launch entry
static __device__ int   g_ptr[NMAX+1];
static __device__ int   g_cur[NMAX];
static __device__ int   g_adj[EMAX];
static __device__ int   g_bsum[160];
static __device__ int   g_boff[160];
static __device__ int   g_done;
static __device__ int   g_flag;
static __device__ int   g_pass;
static __device__ int   g_offs[PTOT];
static __device__ int   g_offt[PTOT];
static __device__ int   g_order[PTOT];
static __device__ __align__(16) float g_virt[64];

// ---------------- setup: copy X, offsets, order, virt norm, degree count ----------------
__global__ void k_setup_count(const float* __restrict__ xs, const float* __restrict__ xt,
                              int nS32, int nTot32,
                              const int* __restrict__ ls, const int* __restrict__ lt,
                              const float* __restrict__ virt,
                              const int* __restrict__ eis, int Es,
                              const int* __restrict__ eit, int Et, int Ns) {
    int gid = blockIdx.x * 256 + threadIdx.x;
    if (gid < nTot32) g_X[gid] = (gid < nS32) ? xs[gid] : xt[gid - nS32];
    if (gid < Es) atomicAdd(&g_deg[eis[Es + gid]], 1);
    else if (gid < Es + Et) atomicAdd(&g_deg[eit[Et + (gid - Es)] + Ns], 1);
    if (blockIdx.x == 0) {
        int tid = threadIdx.x;
        for (int t = tid; t < PTOT; t += 256) {
            int accs = 0, acct = 0;
            for (int p = 0; p < PTOT; p++) {
                int c = (p < t);
                accs += c ? ls[p] : 0;
                acct += c ? lt[p] : 0;
            }
            g_offs[t] = accs;
            g_offt[t] = acct;
            int n_t = ls[t], rank = 0;
            for (int p = 0; p < PTOT; p++) {
                int np = ls[p];
                rank += (np > n_t) || (np == n_t && p < t);
            }
            g_order[rank] = t;
        }
        if (tid < 64) {
            float s = 0.f;
            for (int j = 0; j < 64; j++) { float v = virt[j]; s += v * v; }
            g_virt[tid] = virt[tid] * rsqrtf(fmaxf(s, 1e-24f));
        }
    }
}

// ---------------- one-pass scan: all NB blocks resident, spin barrier ----------------
__global__ __launch_bounds__(1024) void k_scan1(int Ntot, int NB) {
    __shared__ int ws[32];
    __shared__ int s_ticket;
    __shared__ int bs[160];
    int t = threadIdx.x, lane = t & 31, w = t >> 5, bid = blockIdx.x;
    int i = bid * 1024 + t;
    int a = (i < Ntot) ? g_deg[i] : 0;
    if (i < Ntot) g_deg[i] = 0;   // restore invariant for next call
    int v = a;
    #pragma unroll
    for (int d = 1; d < 32; d <<= 1) { int u = __shfl_up_sync(0xffffffffu, v, d); if (lane >= d) v += u; }
    if (lane == 31) ws[w] = v;
    __syncthreads();
    if (w == 0) {
        int x = ws[lane];
        #pragma unroll
        for (int d = 1; d < 32; d <<= 1) { int u = __shfl_up_sync(0xffffffffu, x, d); if (lane >= d) x += u; }
        ws[lane] = x;
    }
    __syncthreads();
    int excl = v - a + (w > 0 ? ws[w - 1] : 0);
    if (i < Ntot) g_ptr[i] = excl;
    if (t == 0) g_bsum[bid] = ws[31];
    __threadfence();
    if (t == 0) s_ticket = atomicAdd(&g_done, 1);
    __syncthreads();
    if (s_ticket == NB - 1) {
        // closer block: scan block sums
        int bv = (t < NB) ? g_bsum[t] : 0;
        bs[t < 160 ? t : 0] = 0;
        __syncthreads();
        if (t < NB) bs[t] = bv;
        __syncthreads();
        for (int d = 1; d < 160; d <<= 1) {
            int x = (t >= d && t < NB) ? bs[t - d] : 0;
            __syncthreads();
            if (t < NB) bs[t] += x;
            __syncthreads();
        }
        if (t < NB) g_boff[t] = bs[t] - bv;
        if (t == NB - 1) g_ptr[Ntot] = bs[t];
        if (t == 0) g_done = 0;
        __threadfence();
        if (t == 0) atomicExch(&g_flag, 1);
    }
    if (t == 0) { while (atomicAdd(&g_flag, 0) == 0) {} }
    __syncthreads();
    if (i < Ntot) {
        int p = g_ptr[i] + g_boff[bid];
        g_ptr[i] = p;
        g_cur[i] = p;
    }
    __threadfence();
    __syncthreads();
    if (t == 0) {
        int p = atomicAdd(&g_pass, 1);
        if (p == NB - 1) { g_pass = 0; atomicExch(&g_flag, 0); }
    }
}

__global__ void k_fill_all(const int* __restrict__ eis, int Es,
                           const int* __restrict__ eit, int Et, int Ns) {
    int e = blockIdx.x * 256 + threadIdx.x;
    if (e < Es) {
        int pos = atomicAdd(&g_cur[eis[Es + e]], 1);
        g_adj[pos] = eis[e];
    } else if (e < Es + Et) {
        int i = e - Es;
        int pos = atomicAdd(&g_cur[eit[Et + i] + Ns], 1);
        g_adj[pos] = eit[i] + Ns;
    }
}

// warp bitonic sort of 32 ints (ascending)
__device__ __forceinline__ int bsort32(int v, int lane) {
    #pragma unroll
    for (int k = 2; k <= 32; k <<= 1) {
        #pragma unroll
        for (int j = k >> 1; j > 0; j >>= 1) {
            int o = __shfl_xor_sync(0xffffffffu, v, j);
            bool up  = ((lane & k) == 0);
            bool low = ((lane & j) == 0);
            v = (up == low) ? min(v, o) : max(v, o);
        }
    }
    return v;
}

// shared GEMM core: As[K][68] x Ws[K][64] -> out rows, 256 threads, 4x4 tiles
// OUT=0: relu, OUT=1: linear, OUT=2: row-normalize
template <int K, int OUT>
__device__ __forceinline__ void gemm_core(const float* As, const float* Ws,
        const float* __restrict__ bias, float* __restrict__ outp, int node0, int Ntot, int tid) {
    int ti = tid >> 4, tj = tid & 15;
    float acc[4][4] = {{0,0,0,0},{0,0,0,0},{0,0,0,0},{0,0,0,0}};
    #pragma unroll 4
    for (int k = 0; k < K; k++) {
        float4 a = *(const float4*)&As[k * 68 + 4 * ti];
        float4 b = *(const float4*)&Ws[k * 64 + 4 * tj];
        acc[0][0] += a.x*b.x; acc[0][1] += a.x*b.y; acc[0][2] += a.x*b.z; acc[0][3] += a.x*b.w;
        acc[1][0] += a.y*b.x; acc[1][1] += a.y*b.y; acc[1][2] += a.y*b.z; acc[1][3] += a.y*b.w;
        acc[2][0] += a.z*b.x; acc[2][1] += a.z*b.y; acc[2][2] += a.z*b.z; acc[2][3] += a.z*b.w;
        acc[3][0] += a.w*b.x; acc[3][1] += a.w*b.y; acc[3][2] += a.w*b.z; acc[3][3] += a.w*b.w;
    }
    float4 bb = *(const float4*)&bias[4 * tj];
    #pragma unroll
    for (int r = 0; r < 4; r++) {
        int node = node0 + 4 * ti + r;
        float4 o;
        o.x = acc[r][0] + bb.x; o.y = acc[r][1] + bb.y;
        o.z = acc[r][2] + bb.z; o.w = acc[r][3] + bb.w;
        if (OUT == 0) {
            o.x = fmaxf(o.x, 0.f); o.y = fmaxf(o.y, 0.f);
            o.z = fmaxf(o.z, 0.f); o.w = fmaxf(o.w, 0.f);
        } else if (OUT == 2) {
            float ss = o.x*o.x + o.y*o.y + o.z*o.z + o.w*o.w;
            #pragma unroll
            for (int d = 1; d < 16; d <<= 1) ss += __shfl_xor_sync(0xffffffffu, ss, d);
            float inv = rsqrtf(fmaxf(ss, 1e-24f));
            o.x *= inv; o.y *= inv; o.z *= inv; o.w *= inv;
        }
        if (node < Ntot) *(float4*)&outp[(size_t)node * 64 + 4 * tj] = o;
    }
}

// ---------- GNN layer 0: sort adj (write back) + gather X + GEMM ----------
__global__ __launch_bounds__(256) void k_gnn0(const float* __restrict__ W0,
        const float* __restrict__ W1, const float* __restrict__ bias, int Ntot) {
    __shared__ float As[64 * 68];
    __shared__ float Ws[64 * 64];
    int node0 = blockIdx.x * 64, tid = threadIdx.x, w = tid >> 5, lane = tid & 31;

    for (int idx = tid; idx < 64 * 64; idx += 256) {
        int k = idx >> 6, f = idx & 63;
        Ws[idx] = (k < 32) ? W0[k * 64 + f] : W1[(k - 32) * 64 + f];
    }
    #pragma unroll
    for (int s = 0; s < 8; s++) {
        int nd = w * 8 + s, node = node0 + nd;
        float agg = 0.f, selfv = 0.f;
        if (node < Ntot) {
            int p0 = __shfl_sync(0xffffffffu, (lane == 0) ? g_ptr[node] : 0, 0);
            int p1 = __shfl_sync(0xffffffffu, (lane == 0) ? g_ptr[node + 1] : 0, 0);
            int deg = p1 - p0;
            if (deg <= 32) {
                int v = (lane < deg) ? g_adj[p0 + lane] : 0x7fffffff;
                v = bsort32(v, lane);
                if (lane < deg) g_adj[p0 + lane] = v;   // write back sorted
                for (int e = 0; e < deg; e++) {
                    int a = __shfl_sync(0xffffffffu, v, e);
                    agg += g_X[(size_t)a * 32 + lane];
                }
            } else {
                if (lane == 0) {
                    for (int a = p0 + 1; a < p1; a++) {
                        int key = g_adj[a]; int b = a - 1;
                        while (b >= p0 && g_adj[b] > key) { g_adj[b + 1] = g_adj[b]; b--; }
                        g_adj[b + 1] = key;
                    }
                }
                __syncwarp();
                for (int e = p0; e < p1; e++) agg += g_X[(size_t)g_adj[e] * 32 + lane];
            }
            selfv = g_X[(size_t)node * 32 + lane];
        }
        As[lane * 68 + nd] = agg;
        As[(lane + 32) * 68 + nd] = selfv;
    }
    __syncthreads();
    gemm_core<64, 0>(As, Ws, bias, g_H1, node0, Ntot, tid);
}

// ---------- GNN layer 1: gather H1 (sorted adj) + GEMM ----------
__global__ __launch_bounds__(256) void k_gnn1(const float* __restrict__ W0,
        const float* __restrict__ W1, const float* __restrict__ bias, int Ntot) {
    extern __shared__ float sm[];
    float* As = sm;              // [128][68]
    float* Ws = sm + 128 * 68;   // [128][64]
    int node0 = blockIdx.x * 64, tid = threadIdx.x, w = tid >> 5, lane = tid & 31;

    for (int idx = tid; idx < 128 * 64; idx += 256) {
        int k = idx >> 6, f = idx & 63;
        Ws[idx] = (k < 64) ? W0[k * 64 + f] : W1[(k - 64) * 64 + f];
    }
    #pragma unroll
    for (int s = 0; s < 8; s++) {
        int nd = w * 8 + s, node = node0 + nd;
        float a0 = 0.f, a1 = 0.f, s0 = 0.f, s1 = 0.f;
        if (node < Ntot) {
            int p0 = __shfl_sync(0xffffffffu, (lane == 0) ? g_ptr[node] : 0, 0);
            int p1 = __shfl_sync(0xffffffffu, (lane == 0) ? g_ptr[node + 1] : 0, 0);
            for (int e = p0; e < p1; e++) {
                int a = g_adj[e];
                size_t r = (size_t)a * 64;
                a0 += g_H1[r + lane];
                a1 += g_H1[r + 32 + lane];
            }
            size_t rn = (size_t)node * 64;
            s0 = g_H1[rn + lane];
            s1 = g_H1[rn + 32 + lane];
        }
        As[lane * 68 + nd]        = a0;
        As[(lane + 32) * 68 + nd] = a1;
        As[(lane + 64) * 68 + nd] = s0;
        As[(lane + 96) * 68 + nd] = s1;
    }
    __syncthreads();
    gemm_core<128, 0>(As, Ws, bias, g_H2, node0, Ntot, tid);
}

// ---------- projection: [X|H1|H2] @ W_e + b_e, normalized ----------
__global__ __launch_bounds__(256) void k_gnn2(const float* __restrict__ We,
        const float* __restrict__ bias, int Ntot) {
    extern __shared__ float sm[];
    float* As = sm;              // [160][68]
    float* Ws = sm + 160 * 68;   // [160][64]
    int node0 = blockIdx.x * 64, tid = threadIdx.x;

    for (int idx = tid; idx < 64 * 160; idx += 256) {
        int nd = idx / 160, k = idx - nd * 160;
        int node = node0 + nd;
        float v = 0.f;
        if (node < Ntot) {
            size_t n64 = (size_t)node * 64, n32 = (size_t)node * 32;
            v = (k < 32) ? g_X[n32 + k]
              : (k < 96) ? g_H1[n64 + k - 32]
                         : g_H2[n64 + k - 96];
        }
        As[k * 68 + nd] = v;
    }
    for (int idx = tid; idx < 160 * 64; idx += 256) Ws[idx] = We[idx];
    __syncthreads();
    gemm_core<160, 2>(As, Ws, bias, g_EMB, node0, Ntot, tid);
}

// ---------------- per-pair: cost/K + Sinkhorn + gamma/cost/geds (512 threads) ----------------
__global__ __launch_bounds__(512) void k_pair(const int* __restrict__ ls, const int* __restrict__ lt,
        int Ns, float* __restrict__ gamma, float* __restrict__ cost, float* __restrict__ geds2) {
    extern __shared__ float sm[];
    float* Km   = sm;               // [192][192]
    float* Ssub = sm + 36864;       // [64][68]
    float* Tsub = Ssub + 4352;      // [64][68]
    float* sqs  = Tsub + 4352;      // [192]
    float* sqt  = sqs + 192;        // [192]
    float* uu   = sqt + 192;        // [192]
    float* vv   = uu + 192;         // [192]
    float* vp   = vv + 192;         // [192] v-pass partials
    float* red  = vp + 192;         // [512]

    int p = g_order[blockIdx.x];
    int tid = threadIdx.x;
    int n = ls[p], m = lt[p], q = 192 - n;
    int offs = g_offs[p], offt = g_offt[p];
    const float* EB = g_EMB;

    for (int i = tid; i < n; i += 512) {
        const float4* r = (const float4*)(EB + (size_t)(offs + i) * 64);
        float s = 0.f;
        #pragma unroll
        for (int k = 0; k < 16; k++) { float4 x = r[k]; s += x.x*x.x + x.y*x.y + x.z*x.z + x.w*x.w; }
        sqs[i] = s;
    }
    for (int j = tid; j < n; j += 512) {
        const float4* r = (j < m) ? (const float4*)(EB + (size_t)(Ns + offt + j) * 64)
                                  : (const float4*)g_virt;
        float s = 0.f;
        #pragma unroll
        for (int k = 0; k < 16; k++) { float4 x = r[k]; s += x.x*x.x + x.y*x.y + x.z*x.z + x.w*x.w; }
        sqt[j] = s;
    }
    for (int i = tid; i < 192; i += 512) {
        uu[i] = 1.0f / 192.0f;
        vv[i] = (i >= n && q > 0) ? (192.0f / (float)q) : 0.f;
    }

    int ti2 = tid >> 4, tj = tid & 15;   // 32 x 16 thread grid, 2x4 micro-tiles
    for (int i0 = 0; i0 < 192; i0 += 64) {
        if (i0 < n) {
            __syncthreads();
            for (int idx = tid; idx < 4096; idx += 512) {
                int nd = idx >> 6, k = idx & 63;
                int i = i0 + nd; if (i >= n) i = n - 1;
                Ssub[k * 68 + nd] = EB[(size_t)(offs + i) * 64 + k];
            }
        }
        for (int j0 = 0; j0 < 192; j0 += 64) {
            if (i0 < n && j0 < n) {
                __syncthreads();
                for (int idx = tid; idx < 4096; idx += 512) {
                    int nd = idx >> 6, k = idx & 63;
                    int j = j0 + nd;
                    const float* r = (j < m) ? (EB + (size_t)(Ns + offt + j) * 64) : g_virt;
                    Tsub[k * 68 + nd] = r[k];
                }
                __syncthreads();
                float acc[2][4] = {{0,0,0,0},{0,0,0,0}};
                #pragma unroll 4
                for (int k = 0; k < 64; k++) {
                    float2 a = *(const float2*)&Ssub[k * 68 + 2 * ti2];
                    float4 b = *(const float4*)&Tsub[k * 68 + 4 * tj];
                    acc[0][0] += a.x*b.x; acc[0][1] += a.x*b.y; acc[0][2] += a.x*b.z; acc[0][3] += a.x*b.w;
                    acc[1][0] += a.y*b.x; acc[1][1] += a.y*b.y; acc[1][2] += a.y*b.z; acc[1][3] += a.y*b.w;
                }
                #pragma unroll
                for (int r = 0; r < 2; r++) {
                    int i = i0 + 2 * ti2 + r;
                    float kv[4];
                    #pragma unroll
                    for (int c = 0; c < 4; c++) {
                        int j = j0 + 4 * tj + c;
                        if (i < n && j < n) {
                            float d = fmaxf(sqs[i] + sqt[j] - 2.0f * acc[r][c], 1e-12f);
                            float cd = d * rsqrtf(d);
                            kv[c] = __expf(-10.0f * cd);
                        } else {
                            kv[c] = ((i >= n) && (j >= n)) ? 1.f : 0.f;
                        }
                    }
                    *(float4*)&Km[i * 192 + j0 + 4 * tj] = make_float4(kv[0], kv[1], kv[2], kv[3]);
                }
            } else {
                #pragma unroll
                for (int r = 0; r < 2; r++) {
                    int i = i0 + 2 * ti2 + r;
                    float kv[4];
                    #pragma unroll
                    for (int c = 0; c < 4; c++) {
                        int j = j0 + 4 * tj + c;
                        kv[c] = ((i >= n) && (j >= n)) ? 1.f : 0.f;
                    }
                    *(float4*)&Km[i * 192 + j0 + 4 * tj] = make_float4(kv[0], kv[1], kv[2], kv[3]);
                }
            }
        }
    }
    __syncthreads();

    // Sinkhorn on the n x n real block; pad u,v stationary; cross K = 0 exactly.
    int w = tid >> 5, lane = tid & 31;
    int nh = (n + 1) >> 1;
    for (int it = 0; it < 8; it++) {
        // v-pass: column j split across two thread groups
        float slo = 0.f;
        if (tid < 192) {
            int j = tid;
            if (j < n) for (int i = 0; i < nh; i++) slo += Km[i * 192 + j] * uu[i];
        } else if (tid >= 256 && tid < 448) {
            int j = tid - 256;
            if (j < n) {
                float s = 0.f;
                for (int i = nh; i < n; i++) s += Km[i * 192 + j] * uu[i];
                vp[j] = s;
            }
        }
        __syncthreads();
        if (tid < n) vv[tid] = 1.0f / (slo + vp[tid]);
        __syncthreads();
        // u-pass: warp per row, 16 warps
        for (int i = w; i < n; i += 16) {
            float s = 0.f;
            for (int j = lane; j < n; j += 32) s += Km[i * 192 + j] * vv[j];
            #pragma unroll
            for (int d = 16; d; d >>= 1) s += __shfl_xor_sync(0xffffffffu, s, d);
            if (lane == 0) uu[i] = 1.0f / s;
        }
        __syncthreads();
    }

    // epilogue: gamma = u K v; cost = -0.1 ln K in-block; geds
    float* costp = cost + (size_t)p * 36864;
    float* gamp  = gamma + (size_t)p * 36864;
    float loc = 0.f;
    for (int idx = tid; idx < 9216; idx += 512) {
        int i = idx / 48, jb = (idx - i * 48) * 4;
        float4 k4 = *(const float4*)&Km[i * 192 + jb];
        float ui = uu[i];
        float kk[4] = {k4.x, k4.y, k4.z, k4.w};
        float gg[4], cc[4];
        #pragma unroll
        for (int c = 0; c < 4; c++) {
            int j = jb + c;
            bool inb = (i < n) && (j < n);
            cc[c] = inb ? (-0.1f * __logf(kk[c]))
                        : (((i >= n) && (j >= n)) ? 0.f : 1000.f);
            gg[c] = ui * kk[c] * vv[j];
            loc += gg[c] * cc[c];
        }
        *(float4*)&gamp[i * 192 + jb]  = make_float4(gg[0], gg[1], gg[2], gg[3]);
        *(float4*)&costp[i * 192 + jb] = make_float4(cc[0], cc[1], cc[2], cc[3]);
    }
    red[tid] = loc;
    __syncthreads();
    #pragma unroll
    for (int s = 256; s; s >>= 1) { if (tid < s) red[tid] += red[tid + s]; __syncthreads(); }
    if (tid == 0) geds2[p] = red[0] / (float)(n + m);
}

extern "C" void kernel_launch(void* const* d_in, const int* in_sizes, int n_in,
                              void* d_out, int out_size) {
    const float* x_s     = (const float*)d_in[0];
    const float* x_t     = (const float*)d_in[1];
    const float* W_rel0  = (const float*)d_in[2];
    const float* b_rel0  = (const float*)d_in[3];
    const float* W_root0 = (const float*)d_in[4];
    const float* W_rel1  = (const float*)d_in[5];
    const float* b_rel1  = (const float*)d_in[6];
    const float* W_root1 = (const float*)d_in[7];
    const float* W_e     = (const float*)d_in[8];
    const float* b_e     = (const float*)d_in[9];
    const float* virt    = (const float*)d_in[10];
    const int* ei_s      = (const int*)d_in[11];
    const int* ei_t      = (const int*)d_in[12];
    const int* len_s     = (const int*)d_in[13];
    const int* len_t     = (const int*)d_in[14];

    int Ns = in_sizes[0] / 32, Nt = in_sizes[1] / 32;
    int Es = in_sizes[11] / 2, Et = in_sizes[12] / 2;
    int Ntot = Ns + Nt;
    int Etot = Es + Et;

    float* out   = (float*)d_out;
    float* gamma = out;
    float* cost  = out + (size_t)PTOT * 36864;
    float* geds2 = cost + (size_t)PTOT * 36864;

    cudaFuncSetAttribute(k_gnn1, cudaFuncAttributeMaxDynamicSharedMemorySize, 128 * 132 * 4);
    cudaFuncSetAttribute(k_gnn2, cudaFuncAttributeMaxDynamicSharedMemorySize, 160 * 132 * 4);
    cudaFuncSetAttribute(k_pair, cudaFuncAttributeMaxDynamicSharedMemorySize, 47040 * 4);

    int NB = (Ntot + 1023) / 1024;
    int gsetup = (Ntot * 32 + 255) / 256;
    if (gsetup < (Etot + 255) / 256) gsetup = (Etot + 255) / 256;

    k_setup_count<<<gsetup, 256>>>(x_s, x_t, Ns * 32, Ntot * 32, len_s, len_t, virt,
                                   ei_s, Es, ei_t, Et, Ns);
    k_scan1<<<NB, 1024>>>(Ntot, NB);
    k_fill_all<<<(Etot + 255) / 256, 256>>>(ei_s, Es, ei_t, Et, Ns);

    int gb = (Ntot + 63) / 64;
    k_gnn0<<<gb, 256>>>(W_rel0, W_root0, b_rel0, Ntot);
    k_gnn1<<<gb, 256, 128 * 132 * 4>>>(W_rel1, W_root1, b_rel1, Ntot);
    k_gnn2<<<gb, 256, 160 * 132 * 4>>>(W_e, b_e, Ntot);

    k_pair<<<PTOT, 512, 47040 * 4>>>(len_s, len_t, Ns, gamma, cost, geds2);
}

// round 6
// speedup vs baseline: 1.4650x; 1.0629x over previous
#include <cuda_runtime.h>
#include <math.h>

#define NMAX 110592
#define EMAX (NMAX*8)
#define PTOT 512

static __device__ __align__(16) float g_X  [NMAX*32];
static __device__ __align__(16) float g_H1 [NMAX*64];
static __device__ __align__(16) float g_EMB[NMAX*64];
static __device__ int   g_deg[NMAX];        // invariant: zero at kernel_launch entry
static __device__ int   g_ptr[NMAX+1];
static __device__ int   g_cur[NMAX];
static __device__ int   g_adj[EMAX];
static __device__ int   g_bsum[160];
static __device__ int   g_boff[160];
static __device__ int   g_done;
static __device__ int   g_pass;
static __device__ int   g_done2;
static __device__ int   g_flag;
static __device__ int   g_flag2;
static __device__ int   g_offs[PTOT];
static __device__ int   g_offt[PTOT];
static __device__ int   g_order[PTOT];
static __device__ __align__(16) float g_virt[64];

// ---------------- setup: copy X, offsets, order, virt norm, degree count ----------------
__global__ void k_setup_count(const float* __restrict__ xs, const float* __restrict__ xt,
                              int nS32, int nTot32,
                              const int* __restrict__ ls, const int* __restrict__ lt,
                              const float* __restrict__ virt,
                              const int* __restrict__ eis, int Es,
                              const int* __restrict__ eit, int Et, int Ns) {
    int gid = blockIdx.x * 256 + threadIdx.x;
    if (gid < nTot32) g_X[gid] = (gid < nS32) ? xs[gid] : xt[gid - nS32];
    if (gid < Es) atomicAdd(&g_deg[eis[Es + gid]], 1);
    else if (gid < Es + Et) atomicAdd(&g_deg[eit[Et + (gid - Es)] + Ns], 1);
    if (blockIdx.x == 0) {
        int tid = threadIdx.x;
        for (int t = tid; t < PTOT; t += 256) {
            int accs = 0, acct = 0;
            for (int p = 0; p < PTOT; p++) {
                int c = (p < t);
                accs += c ? ls[p] : 0;
                acct += c ? lt[p] : 0;
            }
            g_offs[t] = accs;
            g_offt[t] = acct;
            int n_t = ls[t], rank = 0;
            for (int p = 0; p < PTOT; p++) {
                int np = ls[p];
                rank += (np > n_t) || (np == n_t && p < t);
            }
            g_order[rank] = t;
        }
        if (tid < 64) {
            float s = 0.f;
            for (int j = 0; j < 64; j++) { float v = virt[j]; s += v * v; }
            g_virt[tid] = virt[tid] * rsqrtf(fmaxf(s, 1e-24f));
        }
    }
}

// ---------------- scan + CSR fill in one resident kernel (NB <= 148) ----------------
__global__ __launch_bounds__(1024) void k_scanfill(int Ntot, int NB,
        const int* __restrict__ eis, int Es,
        const int* __restrict__ eit, int Et, int Ns, int Etot) {
    __shared__ int ws[32];
    __shared__ int s_t1, s_t2;
    __shared__ int bs[160];
    int t = threadIdx.x, lane = t & 31, w = t >> 5, bid = blockIdx.x;
    int i = bid * 1024 + t;
    int a = (i < Ntot) ? g_deg[i] : 0;
    if (i < Ntot) g_deg[i] = 0;   // restore invariant for next call
    int v = a;
    #pragma unroll
    for (int d = 1; d < 32; d <<= 1) { int u = __shfl_up_sync(0xffffffffu, v, d); if (lane >= d) v += u; }
    if (lane == 31) ws[w] = v;
    __syncthreads();
    if (w == 0) {
        int x = ws[lane];
        #pragma unroll
        for (int d = 1; d < 32; d <<= 1) { int u = __shfl_up_sync(0xffffffffu, x, d); if (lane >= d) x += u; }
        ws[lane] = x;
    }
    __syncthreads();
    int excl = v - a + (w > 0 ? ws[w - 1] : 0);
    if (i < Ntot) g_ptr[i] = excl;
    if (t == 0) g_bsum[bid] = ws[31];
    __threadfence();
    if (t == 0) s_t1 = atomicAdd(&g_done, 1);
    __syncthreads();
    if (s_t1 == NB - 1) {
        int bv = (t < NB) ? g_bsum[t] : 0;
        if (t < 160) bs[t] = (t < NB) ? bv : 0;
        __syncthreads();
        for (int d = 1; d < 160; d <<= 1) {
            int x = (t >= d && t < NB) ? bs[t - d] : 0;
            __syncthreads();
            if (t < NB) bs[t] += x;
            __syncthreads();
        }
        if (t < NB) g_boff[t] = bs[t] - bv;
        if (t == NB - 1) g_ptr[Ntot] = bs[t];
        if (t == 0) { g_done = 0; __threadfence(); atomicExch(&g_flag, 1); }
    }
    if (t == 0) { while (atomicAdd(&g_flag, 0) == 0) {} }
    __syncthreads();
    if (i < Ntot) {
        int p = g_ptr[i] + g_boff[bid];
        g_ptr[i] = p;
        g_cur[i] = p;
    }
    __threadfence();
    __syncthreads();
    if (t == 0) s_t2 = atomicAdd(&g_pass, 1);
    __syncthreads();
    if (s_t2 == NB - 1) {
        if (t == 0) { g_pass = 0; __threadfence(); atomicExch(&g_flag2, 1); }
    }
    if (t == 0) { while (atomicAdd(&g_flag2, 0) == 0) {} }
    __syncthreads();
    // fill phase
    for (int e = bid * 1024 + t; e < Etot; e += NB * 1024) {
        if (e < Es) {
            int pos = atomicAdd(&g_cur[eis[Es + e]], 1);
            g_adj[pos] = eis[e];
        } else {
            int k = e - Es;
            int pos = atomicAdd(&g_cur[eit[Et + k] + Ns], 1);
            g_adj[pos] = eit[k] + Ns;
        }
    }
    __threadfence();
    __syncthreads();
    if (t == 0) {
        int c = atomicAdd(&g_done2, 1);
        if (c == NB - 1) { g_done2 = 0; atomicExch(&g_flag, 0); atomicExch(&g_flag2, 0); }
    }
}

// warp bitonic sort of 32 ints (ascending)
__device__ __forceinline__ int bsort32(int v, int lane) {
    #pragma unroll
    for (int k = 2; k <= 32; k <<= 1) {
        #pragma unroll
        for (int j = k >> 1; j > 0; j >>= 1) {
            int o = __shfl_xor_sync(0xffffffffu, v, j);
            bool up  = ((lane & k) == 0);
            bool low = ((lane & j) == 0);
            v = (up == low) ? min(v, o) : max(v, o);
        }
    }
    return v;
}

// GEMM core: As[K][68] x Ws[K][64], 256 threads, 4x4 tiles
// OUT=0 relu, OUT=2 row-normalize; LOCAL: write to smem tile [64][64]
template <int K, int OUT, bool LOCAL>
__device__ __forceinline__ void gemm_core(const float* As, const float* Ws,
        const float* __restrict__ bias, float* outp, int node0, int Ntot, int tid) {
    int ti = tid >> 4, tj = tid & 15;
    float acc[4][4] = {{0,0,0,0},{0,0,0,0},{0,0,0,0},{0,0,0,0}};
    #pragma unroll 4
    for (int k = 0; k < K; k++) {
        float4 a = *(const float4*)&As[k * 68 + 4 * ti];
        float4 b = *(const float4*)&Ws[k * 64 + 4 * tj];
        acc[0][0] += a.x*b.x; acc[0][1] += a.x*b.y; acc[0][2] += a.x*b.z; acc[0][3] += a.x*b.w;
        acc[1][0] += a.y*b.x; acc[1][1] += a.y*b.y; acc[1][2] += a.y*b.z; acc[1][3] += a.y*b.w;
        acc[2][0] += a.z*b.x; acc[2][1] += a.z*b.y; acc[2][2] += a.z*b.z; acc[2][3] += a.z*b.w;
        acc[3][0] += a.w*b.x; acc[3][1] += a.w*b.y; acc[3][2] += a.w*b.z; acc[3][3] += a.w*b.w;
    }
    float4 bb = *(const float4*)&bias[4 * tj];
    #pragma unroll
    for (int r = 0; r < 4; r++) {
        int node = node0 + 4 * ti + r;
        float4 o;
        o.x = acc[r][0] + bb.x; o.y = acc[r][1] + bb.y;
        o.z = acc[r][2] + bb.z; o.w = acc[r][3] + bb.w;
        if (OUT == 0) {
            o.x = fmaxf(o.x, 0.f); o.y = fmaxf(o.y, 0.f);
            o.z = fmaxf(o.z, 0.f); o.w = fmaxf(o.w, 0.f);
        } else if (OUT == 2) {
            float ss = o.x*o.x + o.y*o.y + o.z*o.z + o.w*o.w;
            #pragma unroll
            for (int d = 1; d < 16; d <<= 1) ss += __shfl_xor_sync(0xffffffffu, ss, d);
            float inv = rsqrtf(fmaxf(ss, 1e-24f));
            o.x *= inv; o.y *= inv; o.z *= inv; o.w *= inv;
        }
        if (LOCAL) {
            *(float4*)&outp[(4 * ti + r) * 64 + 4 * tj] = o;
        } else {
            if (node < Ntot) *(float4*)&outp[(size_t)node * 64 + 4 * tj] = o;
        }
    }
}

// ---------- GNN layer 0: sort adj (write back) + gather X + GEMM ----------
__global__ __launch_bounds__(256) void k_gnn0(const float* __restrict__ W0,
        const float* __restrict__ W1, const float* __restrict__ bias, int Ntot) {
    __shared__ float As[64 * 68];
    __shared__ float Ws[64 * 64];
    int node0 = blockIdx.x * 64, tid = threadIdx.x, w = tid >> 5, lane = tid & 31;

    for (int idx = tid; idx < 64 * 64; idx += 256) {
        int k = idx >> 6, f = idx & 63;
        Ws[idx] = (k < 32) ? W0[k * 64 + f] : W1[(k - 32) * 64 + f];
    }
    #pragma unroll
    for (int s = 0; s < 8; s++) {
        int nd = w * 8 + s, node = node0 + nd;
        float agg = 0.f, selfv = 0.f;
        if (node < Ntot) {
            int p0 = __shfl_sync(0xffffffffu, (lane == 0) ? g_ptr[node] : 0, 0);
            int p1 = __shfl_sync(0xffffffffu, (lane == 0) ? g_ptr[node + 1] : 0, 0);
            int deg = p1 - p0;
            if (deg <= 32) {
                int v = (lane < deg) ? g_adj[p0 + lane] : 0x7fffffff;
                v = bsort32(v, lane);
                if (lane < deg) g_adj[p0 + lane] = v;   // write back sorted
                for (int e = 0; e < deg; e++) {
                    int a = __shfl_sync(0xffffffffu, v, e);
                    agg += g_X[(size_t)a * 32 + lane];
                }
            } else {
                if (lane == 0) {
                    for (int a = p0 + 1; a < p1; a++) {
                        int key = g_adj[a]; int b = a - 1;
                        while (b >= p0 && g_adj[b] > key) { g_adj[b + 1] = g_adj[b]; b--; }
                        g_adj[b + 1] = key;
                    }
                }
                __syncwarp();
                for (int e = p0; e < p1; e++) agg += g_X[(size_t)g_adj[e] * 32 + lane];
            }
            selfv = g_X[(size_t)node * 32 + lane];
        }
        As[lane * 68 + nd] = agg;
        As[(lane + 32) * 68 + nd] = selfv;
    }
    __syncthreads();
    gemm_core<64, 0, false>(As, Ws, bias, g_H1, node0, Ntot, tid);
}

// ---------- fused GNN layer 1 + projection: H2 stays in smem ----------
__global__ __launch_bounds__(256) void k_gnn12(
        const float* __restrict__ Wr1, const float* __restrict__ Wo1,
        const float* __restrict__ b1,
        const float* __restrict__ We, const float* __restrict__ be, int Ntot) {
    extern __shared__ float sm[];
    float* H2s = sm;              // [64][64] = 4096
    float* As  = sm + 4096;       // up to [160][68] = 10880
    float* Ws  = As + 10880;      // up to [160][64] = 10240
    int node0 = blockIdx.x * 64, tid = threadIdx.x, w = tid >> 5, lane = tid & 31;

    // phase A: H2 = relu(agg(H1)@Wr1 + H1@Wo1 + b1), K=128
    for (int idx = tid; idx < 128 * 64; idx += 256) {
        int k = idx >> 6, f = idx & 63;
        Ws[idx] = (k < 64) ? Wr1[k * 64 + f] : Wo1[(k - 64) * 64 + f];
    }
    #pragma unroll
    for (int s = 0; s < 8; s++) {
        int nd = w * 8 + s, node = node0 + nd;
        float a0 = 0.f, a1 = 0.f, s0 = 0.f, s1 = 0.f;
        if (node < Ntot) {
            int p0 = __shfl_sync(0xffffffffu, (lane == 0) ? g_ptr[node] : 0, 0);
            int p1 = __shfl_sync(0xffffffffu, (lane == 0) ? g_ptr[node + 1] : 0, 0);
            for (int e = p0; e < p1; e++) {
                size_t r = (size_t)g_adj[e] * 64;
                a0 += g_H1[r + lane];
                a1 += g_H1[r + 32 + lane];
            }
            size_t rn = (size_t)node * 64;
            s0 = g_H1[rn + lane];
            s1 = g_H1[rn + 32 + lane];
        }
        As[lane * 68 + nd]        = a0;
        As[(lane + 32) * 68 + nd] = a1;
        As[(lane + 64) * 68 + nd] = s0;
        As[(lane + 96) * 68 + nd] = s1;
    }
    __syncthreads();
    gemm_core<128, 0, true>(As, Ws, b1, H2s, node0, Ntot, tid);
    __syncthreads();

    // phase B: EMB = normalize([X|H1|H2] @ We + be), K=160
    for (int idx = tid; idx < 64 * 160; idx += 256) {
        int nd = idx / 160, k = idx - nd * 160;
        int node = node0 + nd;
        float v = 0.f;
        if (node < Ntot) {
            v = (k < 32)  ? g_X[(size_t)node * 32 + k]
              : (k < 96)  ? g_H1[(size_t)node * 64 + k - 32]
                          : H2s[nd * 64 + k - 96];
        }
        As[k * 68 + nd] = v;
    }
    for (int idx = tid; idx < 160 * 64; idx += 256) Ws[idx] = We[idx];
    __syncthreads();
    gemm_core<160, 2, false>(As, Ws, be, g_EMB, node0, Ntot, tid);
}

// ---------------- per-pair: cost/K + Sinkhorn + gamma/cost/geds (512 threads) ----------------
__global__ __launch_bounds__(512) void k_pair(const int* __restrict__ ls, const int* __restrict__ lt,
        int Ns, float* __restrict__ gamma, float* __restrict__ cost, float* __restrict__ geds2) {
    extern __shared__ float sm[];
    float* Km   = sm;               // [192][192]
    float* Ssub = sm + 36864;       // [64][68]
    float* Tsub = Ssub + 4352;      // 2 x [64][68]
    float* sqs  = Tsub + 8704;      // [192]
    float* sqt  = sqs + 192;        // [192]
    float* uu   = sqt + 192;        // [192]
    float* vv   = uu + 192;         // [192]
    float* vp   = vv + 192;         // [192]
    float* red  = vp + 192;         // [512]

    int p = g_order[blockIdx.x];
    int tid = threadIdx.x;
    int n = ls[p], m = lt[p], q = 192 - n;
    int offs = g_offs[p], offt = g_offt[p];
    const float* EB = g_EMB;

    for (int i = tid; i < n; i += 512) {
        const float4* r = (const float4*)(EB + (size_t)(offs + i) * 64);
        float s = 0.f;
        #pragma unroll
        for (int k = 0; k < 16; k++) { float4 x = r[k]; s += x.x*x.x + x.y*x.y + x.z*x.z + x.w*x.w; }
        sqs[i] = s;
    }
    for (int j = tid; j < n; j += 512) {
        const float4* r = (j < m) ? (const float4*)(EB + (size_t)(Ns + offt + j) * 64)
                                  : (const float4*)g_virt;
        float s = 0.f;
        #pragma unroll
        for (int k = 0; k < 16; k++) { float4 x = r[k]; s += x.x*x.x + x.y*x.y + x.z*x.z + x.w*x.w; }
        sqt[j] = s;
    }
    for (int i = tid; i < 192; i += 512) {
        uu[i] = 1.0f / 192.0f;
        vv[i] = (i >= n && q > 0) ? (192.0f / (float)q) : 0.f;
    }

    // cost/K for real tiles only (two 64x64 tiles concurrently, one per 256-thread group)
    int g = tid >> 8, lt5 = tid & 255;
    int ti = lt5 >> 4, tj = lt5 & 15;
    float* Tg = Tsub + g * 4352;
    int ntile = (n + 63) >> 6;

    for (int it_i = 0; it_i < ntile; it_i++) {
        int i0 = it_i << 6;
        __syncthreads();
        for (int idx = tid; idx < 4096; idx += 512) {
            int nd = idx >> 6, k = idx & 63;
            int i = i0 + nd; if (i >= n) i = n - 1;
            Ssub[k * 68 + nd] = EB[(size_t)(offs + i) * 64 + k];
        }
        for (int jj = 0; jj < ntile; jj += 2) {
            int jt = jj + g;
            bool mine = (jt < ntile);
            int j0 = jt << 6;
            __syncthreads();
            if (mine) {
                for (int idx = lt5; idx < 4096; idx += 256) {
                    int nd = idx >> 6, k = idx & 63;
                    int j = j0 + nd;
                    const float* r = (j < m) ? (EB + (size_t)(Ns + offt + j) * 64) : g_virt;
                    Tg[k * 68 + nd] = r[k];
                }
            }
            __syncthreads();
            if (mine) {
                float acc[4][4] = {{0,0,0,0},{0,0,0,0},{0,0,0,0},{0,0,0,0}};
                #pragma unroll 4
                for (int k = 0; k < 64; k++) {
                    float4 a = *(const float4*)&Ssub[k * 68 + 4 * ti];
                    float4 b = *(const float4*)&Tg[k * 68 + 4 * tj];
                    acc[0][0] += a.x*b.x; acc[0][1] += a.x*b.y; acc[0][2] += a.x*b.z; acc[0][3] += a.x*b.w;
                    acc[1][0] += a.y*b.x; acc[1][1] += a.y*b.y; acc[1][2] += a.y*b.z; acc[1][3] += a.y*b.w;
                    acc[2][0] += a.z*b.x; acc[2][1] += a.z*b.y; acc[2][2] += a.z*b.z; acc[2][3] += a.z*b.w;
                    acc[3][0] += a.w*b.x; acc[3][1] += a.w*b.y; acc[3][2] += a.w*b.z; acc[3][3] += a.w*b.w;
                }
                #pragma unroll
                for (int r = 0; r < 4; r++) {
                    int i = i0 + 4 * ti + r;
                    float kv[4];
                    #pragma unroll
                    for (int c = 0; c < 4; c++) {
                        int j = j0 + 4 * tj + c;
                        if (i < n && j < n) {
                            float d = fmaxf(sqs[i] + sqt[j] - 2.0f * acc[r][c], 1e-12f);
                            float cd = d * rsqrtf(d);
                            kv[c] = __expf(-10.0f * cd);
                        } else {
                            kv[c] = ((i >= n) && (j >= n)) ? 1.f : 0.f;
                        }
                    }
                    *(float4*)&Km[i * 192 + j0 + 4 * tj] = make_float4(kv[0], kv[1], kv[2], kv[3]);
                }
            }
        }
    }
    __syncthreads();

    // Sinkhorn on the n x n real block; pad u,v stationary; cross K = 0 exactly.
    int w = tid >> 5, lane = tid & 31;
    int nh = (n + 1) >> 1;
    for (int it = 0; it < 8; it++) {
        float slo = 0.f;
        if (tid < 192) {
            int j = tid;
            if (j < n) for (int i = 0; i < nh; i++) slo += Km[i * 192 + j] * uu[i];
        } else if (tid < 384) {
            int j = tid - 192;
            if (j < n) {
                float s = 0.f;
                for (int i = nh; i < n; i++) s += Km[i * 192 + j] * uu[i];
                vp[j] = s;
            }
        }
        __syncthreads();
        if (tid < n) vv[tid] = 1.0f / (slo + vp[tid]);
        __syncthreads();
        for (int i = w; i < n; i += 16) {
            float s = 0.f;
            for (int j = lane; j < n; j += 32) s += Km[i * 192 + j] * vv[j];
            #pragma unroll
            for (int d = 16; d; d >>= 1) s += __shfl_xor_sync(0xffffffffu, s, d);
            if (lane == 0) uu[i] = 1.0f / s;
        }
        __syncthreads();
    }

    // epilogue: gamma = u K v; cost = -0.1 ln K in-block, pattern elsewhere; geds
    float* costp = cost + (size_t)p * 36864;
    float* gamp  = gamma + (size_t)p * 36864;
    float loc = 0.f;
    for (int idx = tid; idx < 9216; idx += 512) {
        int i = idx / 48, jb = (idx - i * 48) * 4;
        float4 k4 = *(const float4*)&Km[i * 192 + jb];   // garbage outside real tiles: discarded
        float ui = uu[i];
        float kk[4] = {k4.x, k4.y, k4.z, k4.w};
        float gg[4], cc[4];
        #pragma unroll
        for (int c = 0; c < 4; c++) {
            int j = jb + c;
            bool inb = (i < n) && (j < n);
            bool pad = (i >= n) && (j >= n);
            float kv = inb ? kk[c] : (pad ? 1.f : 0.f);
            cc[c] = inb ? (-0.1f * __logf(kk[c])) : (pad ? 0.f : 1000.f);
            gg[c] = ui * kv * vv[j];
            loc += gg[c] * cc[c];
        }
        *(float4*)&gamp[i * 192 + jb]  = make_float4(gg[0], gg[1], gg[2], gg[3]);
        *(float4*)&costp[i * 192 + jb] = make_float4(cc[0], cc[1], cc[2], cc[3]);
    }
    red[tid] = loc;
    __syncthreads();
    #pragma unroll
    for (int s = 256; s; s >>= 1) { if (tid < s) red[tid] += red[tid + s]; __syncthreads(); }
    if (tid == 0) geds2[p] = red[0] / (float)(n + m);
}

extern "C" void kernel_launch(void* const* d_in, const int* in_sizes, int n_in,
                              void* d_out, int out_size) {
    const float* x_s     = (const float*)d_in[0];
    const float* x_t     = (const float*)d_in[1];
    const float* W_rel0  = (const float*)d_in[2];
    const float* b_rel0  = (const float*)d_in[3];
    const float* W_root0 = (const float*)d_in[4];
    const float* W_rel1  = (const float*)d_in[5];
    const float* b_rel1  = (const float*)d_in[6];
    const float* W_root1 = (const float*)d_in[7];
    const float* W_e     = (const float*)d_in[8];
    const float* b_e     = (const float*)d_in[9];
    const float* virt    = (const float*)d_in[10];
    const int* ei_s      = (const int*)d_in[11];
    const int* ei_t      = (const int*)d_in[12];
    const int* len_s     = (const int*)d_in[13];
    const int* len_t     = (const int*)d_in[14];

    int Ns = in_sizes[0] / 32, Nt = in_sizes[1] / 32;
    int Es = in_sizes[11] / 2, Et = in_sizes[12] / 2;
    int Ntot = Ns + Nt;
    int Etot = Es + Et;

    float* out   = (float*)d_out;
    float* gamma = out;
    float* cost  = out + (size_t)PTOT * 36864;
    float* geds2 = cost + (size_t)PTOT * 36864;

    cudaFuncSetAttribute(k_gnn12, cudaFuncAttributeMaxDynamicSharedMemorySize, 25216 * 4);
    cudaFuncSetAttribute(k_pair,  cudaFuncAttributeMaxDynamicSharedMemorySize, 51392 * 4);

    int NB = (Ntot + 1023) / 1024;
    int gsetup = (Ntot * 32 + 255) / 256;
    if (gsetup < (Etot + 255) / 256) gsetup = (Etot + 255) / 256;

    k_setup_count<<<gsetup, 256>>>(x_s, x_t, Ns * 32, Ntot * 32, len_s, len_t, virt,
                                   ei_s, Es, ei_t, Et, Ns);
    k_scanfill<<<NB, 1024>>>(Ntot, NB, ei_s, Es, ei_t, Et, Ns, Etot);

    int gb = (Ntot + 63) / 64;
    k_gnn0<<<gb, 256>>>(W_rel0, W_root0, b_rel0, Ntot);
    k_gnn12<<<gb, 256, 25216 * 4>>>(W_rel1, W_root1, b_rel1, W_e, b_e, Ntot);

    k_pair<<<PTOT, 512, 51392 * 4>>>(len_s, len_t, Ns, gamma, cost, geds2);
}

// round 7
// speedup vs baseline: 1.4774x; 1.0084x over previous
#include <cuda_runtime.h>
#include <math.h>

#define NMAX 110592
#define EMAX (NMAX*8)
#define PTOT 512

static __device__ __align__(16) float g_X  [NMAX*32];
static __device__ __align__(16) float g_H1 [NMAX*64];
static __device__ __align__(16) float g_EMB[NMAX*64];
static __device__ int   g_deg[NMAX];        // invariant: zero at kernel_launch entry
static __device__ int   g_ptr[NMAX+1];
static __device__ int   g_cur[NMAX];
static __device__ int   g_adj[EMAX];
static __device__ int   g_bsum[160];
static __device__ int   g_boff[160];
static __device__ int   g_cnt;
static __device__ int   g_done;
static __device__ int   g_pass;
static __device__ int   g_done2;
static __device__ int   g_flag0;
static __device__ int   g_flag;
static __device__ int   g_flag2;
static __device__ int   g_offs[PTOT];
static __device__ int   g_offt[PTOT];
static __device__ int   g_order[PTOT];
static __device__ __align__(16) float g_virt[64];

// ---------------- one resident kernel: copy X / count / offsets / scan / fill ----------------
__global__ __launch_bounds__(1024) void k_all(
        const float* __restrict__ xs, const float* __restrict__ xt,
        int nS32, int nTot32,
        const int* __restrict__ ls, const int* __restrict__ lt,
        const float* __restrict__ virt,
        const int* __restrict__ eis, int Es,
        const int* __restrict__ eit, int Et, int Ns,
        int Ntot, int NB, int Etot) {
    __shared__ int ws[32];
    __shared__ int s_t0, s_t1, s_t2;
    __shared__ int bs[160];
    int t = threadIdx.x, lane = t & 31, w = t >> 5, bid = blockIdx.x;
    int stride = NB * 1024;

    // phase 0: copy X, count degrees, block0 computes offsets/order/virt
    for (int i = bid * 1024 + t; i < nTot32; i += stride)
        g_X[i] = (i < nS32) ? xs[i] : xt[i - nS32];
    for (int e = bid * 1024 + t; e < Etot; e += stride) {
        if (e < Es) atomicAdd(&g_deg[eis[Es + e]], 1);
        else { int k = e - Es; atomicAdd(&g_deg[eit[Et + k] + Ns], 1); }
    }
    if (bid == 0) {
        if (t < PTOT) {
            int accs = 0, acct = 0;
            for (int p = 0; p < PTOT; p++) {
                int c = (p < t);
                accs += c ? ls[p] : 0;
                acct += c ? lt[p] : 0;
            }
            g_offs[t] = accs;
            g_offt[t] = acct;
            int n_t = ls[t], rank = 0;
            for (int p = 0; p < PTOT; p++) {
                int np = ls[p];
                rank += (np > n_t) || (np == n_t && p < t);
            }
            g_order[rank] = t;
        }
        if (t < 64) {
            float s = 0.f;
            for (int j = 0; j < 64; j++) { float v = virt[j]; s += v * v; }
            g_virt[t] = virt[t] * rsqrtf(fmaxf(s, 1e-24f));
        }
    }
    __threadfence();
    if (t == 0) s_t0 = atomicAdd(&g_cnt, 1);
    __syncthreads();
    if (s_t0 == NB - 1) {
        if (t == 0) { g_cnt = 0; __threadfence(); atomicExch(&g_flag0, 1); }
    }
    if (t == 0) { while (atomicAdd(&g_flag0, 0) == 0) {} }
    __syncthreads();

    // phase 1: block-local scan of degrees
    int i = bid * 1024 + t;
    int a = (i < Ntot) ? g_deg[i] : 0;
    if (i < Ntot) g_deg[i] = 0;   // restore invariant for next call
    int v = a;
    #pragma unroll
    for (int d = 1; d < 32; d <<= 1) { int u = __shfl_up_sync(0xffffffffu, v, d); if (lane >= d) v += u; }
    if (lane == 31) ws[w] = v;
    __syncthreads();
    if (w == 0) {
        int x = ws[lane];
        #pragma unroll
        for (int d = 1; d < 32; d <<= 1) { int u = __shfl_up_sync(0xffffffffu, x, d); if (lane >= d) x += u; }
        ws[lane] = x;
    }
    __syncthreads();
    int excl = v - a + (w > 0 ? ws[w - 1] : 0);
    if (i < Ntot) g_ptr[i] = excl;
    if (t == 0) g_bsum[bid] = ws[31];
    __threadfence();
    if (t == 0) s_t1 = atomicAdd(&g_done, 1);
    __syncthreads();
    if (s_t1 == NB - 1) {
        int bv = (t < NB) ? g_bsum[t] : 0;
        if (t < 160) bs[t] = (t < NB) ? bv : 0;
        __syncthreads();
        for (int d = 1; d < 160; d <<= 1) {
            int x = (t >= d && t < NB) ? bs[t - d] : 0;
            __syncthreads();
            if (t < NB) bs[t] += x;
            __syncthreads();
        }
        if (t < NB) g_boff[t] = bs[t] - bv;
        if (t == NB - 1) g_ptr[Ntot] = bs[t];
        if (t == 0) { g_done = 0; __threadfence(); atomicExch(&g_flag, 1); }
    }
    if (t == 0) { while (atomicAdd(&g_flag, 0) == 0) {} }
    __syncthreads();
    if (i < Ntot) {
        int p = g_ptr[i] + g_boff[bid];
        g_ptr[i] = p;
        g_cur[i] = p;
    }
    __threadfence();
    __syncthreads();
    if (t == 0) s_t2 = atomicAdd(&g_pass, 1);
    __syncthreads();
    if (s_t2 == NB - 1) {
        if (t == 0) { g_pass = 0; __threadfence(); atomicExch(&g_flag2, 1); }
    }
    if (t == 0) { while (atomicAdd(&g_flag2, 0) == 0) {} }
    __syncthreads();

    // phase 2: fill CSR
    for (int e = bid * 1024 + t; e < Etot; e += stride) {
        if (e < Es) {
            int pos = atomicAdd(&g_cur[eis[Es + e]], 1);
            g_adj[pos] = eis[e];
        } else {
            int k = e - Es;
            int pos = atomicAdd(&g_cur[eit[Et + k] + Ns], 1);
            g_adj[pos] = eit[k] + Ns;
        }
    }
    __threadfence();
    __syncthreads();
    if (t == 0) {
        int c = atomicAdd(&g_done2, 1);
        if (c == NB - 1) {
            g_done2 = 0;
            atomicExch(&g_flag0, 0);
            atomicExch(&g_flag, 0);
            atomicExch(&g_flag2, 0);
        }
    }
}

// warp bitonic sort of 32 ints (ascending)
__device__ __forceinline__ int bsort32(int v, int lane) {
    #pragma unroll
    for (int k = 2; k <= 32; k <<= 1) {
        #pragma unroll
        for (int j = k >> 1; j > 0; j >>= 1) {
            int o = __shfl_xor_sync(0xffffffffu, v, j);
            bool up  = ((lane & k) == 0);
            bool low = ((lane & j) == 0);
            v = (up == low) ? min(v, o) : max(v, o);
        }
    }
    return v;
}

// accumulate: acc += As[K][68] x Ws[K][64] for this thread's 4x4 tile
template <int K>
__device__ __forceinline__ void gemm_acc(const float* As, const float* Ws,
                                         float acc[4][4], int tid) {
    int ti = tid >> 4, tj = tid & 15;
    #pragma unroll 4
    for (int k = 0; k < K; k++) {
        float4 a = *(const float4*)&As[k * 68 + 4 * ti];
        float4 b = *(const float4*)&Ws[k * 64 + 4 * tj];
        acc[0][0] += a.x*b.x; acc[0][1] += a.x*b.y; acc[0][2] += a.x*b.z; acc[0][3] += a.x*b.w;
        acc[1][0] += a.y*b.x; acc[1][1] += a.y*b.y; acc[1][2] += a.y*b.z; acc[1][3] += a.y*b.w;
        acc[2][0] += a.z*b.x; acc[2][1] += a.z*b.y; acc[2][2] += a.z*b.z; acc[2][3] += a.z*b.w;
        acc[3][0] += a.w*b.x; acc[3][1] += a.w*b.y; acc[3][2] += a.w*b.z; acc[3][3] += a.w*b.w;
    }
}

// ---------- GNN layer 0: sort adj (write back) + gather X + GEMM ----------
__global__ __launch_bounds__(256) void k_gnn0(const float* __restrict__ W0,
        const float* __restrict__ W1, const float* __restrict__ bias, int Ntot) {
    __shared__ float As[64 * 68];
    __shared__ float Ws[64 * 64];
    int node0 = blockIdx.x * 64, tid = threadIdx.x, w = tid >> 5, lane = tid & 31;

    for (int idx = tid; idx < 64 * 64; idx += 256) {
        int k = idx >> 6, f = idx & 63;
        Ws[idx] = (k < 32) ? W0[k * 64 + f] : W1[(k - 32) * 64 + f];
    }
    #pragma unroll
    for (int s = 0; s < 8; s++) {
        int nd = w * 8 + s, node = node0 + nd;
        float agg = 0.f, selfv = 0.f;
        if (node < Ntot) {
            int p0 = __shfl_sync(0xffffffffu, (lane == 0) ? g_ptr[node] : 0, 0);
            int p1 = __shfl_sync(0xffffffffu, (lane == 0) ? g_ptr[node + 1] : 0, 0);
            int deg = p1 - p0;
            if (deg <= 32) {
                int v = (lane < deg) ? g_adj[p0 + lane] : 0x7fffffff;
                v = bsort32(v, lane);
                if (lane < deg) g_adj[p0 + lane] = v;   // write back sorted
                for (int e = 0; e < deg; e++) {
                    int a = __shfl_sync(0xffffffffu, v, e);
                    agg += g_X[(size_t)a * 32 + lane];
                }
            } else {
                if (lane == 0) {
                    for (int a = p0 + 1; a < p1; a++) {
                        int key = g_adj[a]; int b = a - 1;
                        while (b >= p0 && g_adj[b] > key) { g_adj[b + 1] = g_adj[b]; b--; }
                        g_adj[b + 1] = key;
                    }
                }
                __syncwarp();
                for (int e = p0; e < p1; e++) agg += g_X[(size_t)g_adj[e] * 32 + lane];
            }
            selfv = g_X[(size_t)node * 32 + lane];
        }
        As[lane * 68 + nd] = agg;
        As[(lane + 32) * 68 + nd] = selfv;
    }
    __syncthreads();
    {
        int ti = tid >> 4, tj = tid & 15;
        float acc[4][4] = {{0,0,0,0},{0,0,0,0},{0,0,0,0},{0,0,0,0}};
        gemm_acc<64>(As, Ws, acc, tid);
        float4 bb = *(const float4*)&bias[4 * tj];
        #pragma unroll
        for (int r = 0; r < 4; r++) {
            int node = node0 + 4 * ti + r;
            float4 o;
            o.x = fmaxf(acc[r][0] + bb.x, 0.f); o.y = fmaxf(acc[r][1] + bb.y, 0.f);
            o.z = fmaxf(acc[r][2] + bb.z, 0.f); o.w = fmaxf(acc[r][3] + bb.w, 0.f);
            if (node < Ntot) *(float4*)&g_H1[(size_t)node * 64 + 4 * tj] = o;
        }
    }
}

// ---------- fused GNN layer 1 + projection, chunked-K (3 CTAs/SM) ----------
__global__ __launch_bounds__(256) void k_gnn12(
        const float* __restrict__ Wr1, const float* __restrict__ Wo1,
        const float* __restrict__ b1,
        const float* __restrict__ We, const float* __restrict__ be, int Ntot) {
    extern __shared__ float sm[];
    float* A1  = sm;              // [64][68] = 4352
    float* A2  = sm + 4352;       // [64][68] = 4352 (H1 self, reused in phase B)
    float* H2s = sm + 8704;       // [64][68] node-major = 4352
    float* Ws  = sm + 13056;      // [64][64] = 4096
    int node0 = blockIdx.x * 64, tid = threadIdx.x, w = tid >> 5, lane = tid & 31;
    int ti = tid >> 4, tj = tid & 15;

    // stage agg(H1) -> A1, H1 self -> A2; Ws <- Wr1
    #pragma unroll
    for (int s = 0; s < 8; s++) {
        int nd = w * 8 + s, node = node0 + nd;
        float a0 = 0.f, a1 = 0.f, s0 = 0.f, s1 = 0.f;
        if (node < Ntot) {
            int p0 = __shfl_sync(0xffffffffu, (lane == 0) ? g_ptr[node] : 0, 0);
            int p1 = __shfl_sync(0xffffffffu, (lane == 0) ? g_ptr[node + 1] : 0, 0);
            for (int e = p0; e < p1; e++) {
                size_t r = (size_t)g_adj[e] * 64;
                a0 += g_H1[r + lane];
                a1 += g_H1[r + 32 + lane];
            }
            size_t rn = (size_t)node * 64;
            s0 = g_H1[rn + lane];
            s1 = g_H1[rn + 32 + lane];
        }
        A1[lane * 68 + nd]        = a0;
        A1[(lane + 32) * 68 + nd] = a1;
        A2[lane * 68 + nd]        = s0;
        A2[(lane + 32) * 68 + nd] = s1;
    }
    for (int idx = tid; idx < 4096; idx += 256) Ws[idx] = Wr1[idx];
    __syncthreads();

    float acc[4][4] = {{0,0,0,0},{0,0,0,0},{0,0,0,0},{0,0,0,0}};
    gemm_acc<64>(A1, Ws, acc, tid);
    __syncthreads();
    for (int idx = tid; idx < 4096; idx += 256) Ws[idx] = Wo1[idx];
    __syncthreads();
    gemm_acc<64>(A2, Ws, acc, tid);
    // bias + relu -> H2s (node-major, stride 68)
    {
        float4 bb = *(const float4*)&b1[4 * tj];
        #pragma unroll
        for (int r = 0; r < 4; r++) {
            float4 o;
            o.x = fmaxf(acc[r][0] + bb.x, 0.f); o.y = fmaxf(acc[r][1] + bb.y, 0.f);
            o.z = fmaxf(acc[r][2] + bb.z, 0.f); o.w = fmaxf(acc[r][3] + bb.w, 0.f);
            *(float4*)&H2s[(4 * ti + r) * 68 + 4 * tj] = o;
        }
    }
    __syncthreads();

    // phase B: EMB = normalize([X | H1 | H2] @ We + be)
    float acc2[4][4] = {{0,0,0,0},{0,0,0,0},{0,0,0,0},{0,0,0,0}};
    // chunk 1: X (K=32), Ws <- We rows 0..31
    for (int idx = tid; idx < 2048; idx += 256) Ws[idx] = We[idx];
    for (int idx = tid; idx < 2048; idx += 256) {
        int nd = idx >> 5, k = idx & 31;
        int node = node0 + nd;
        A1[k * 68 + nd] = (node < Ntot) ? g_X[(size_t)node * 32 + k] : 0.f;
    }
    __syncthreads();
    gemm_acc<32>(A1, Ws, acc2, tid);
    __syncthreads();
    // chunk 2: H1 self (A2), Ws <- We rows 32..95; also A1 <- transpose(H2s)
    for (int idx = tid; idx < 4096; idx += 256) Ws[idx] = We[32 * 64 + idx];
    for (int idx = tid; idx < 4096; idx += 256) {
        int nd = idx >> 6, k = idx & 63;
        A1[k * 68 + nd] = H2s[nd * 68 + k];
    }
    __syncthreads();
    gemm_acc<64>(A2, Ws, acc2, tid);
    __syncthreads();
    // chunk 3: H2 (A1), Ws <- We rows 96..159
    for (int idx = tid; idx < 4096; idx += 256) Ws[idx] = We[96 * 64 + idx];
    __syncthreads();
    gemm_acc<64>(A1, Ws, acc2, tid);
    // bias + normalize + write
    {
        float4 bb = *(const float4*)&be[4 * tj];
        #pragma unroll
        for (int r = 0; r < 4; r++) {
            int node = node0 + 4 * ti + r;
            float4 o;
            o.x = acc2[r][0] + bb.x; o.y = acc2[r][1] + bb.y;
            o.z = acc2[r][2] + bb.z; o.w = acc2[r][3] + bb.w;
            float ss = o.x*o.x + o.y*o.y + o.z*o.z + o.w*o.w;
            #pragma unroll
            for (int d = 1; d < 16; d <<= 1) ss += __shfl_xor_sync(0xffffffffu, ss, d);
            float inv = rsqrtf(fmaxf(ss, 1e-24f));
            o.x *= inv; o.y *= inv; o.z *= inv; o.w *= inv;
            if (node < Ntot) *(float4*)&g_EMB[(size_t)node * 64 + 4 * tj] = o;
        }
    }
}

// ---------------- per-pair: cost/K + Sinkhorn + gamma/cost/geds (512 threads) ----------------
__global__ __launch_bounds__(512) void k_pair(const int* __restrict__ ls, const int* __restrict__ lt,
        int Ns, float* __restrict__ gamma, float* __restrict__ cost, float* __restrict__ geds2) {
    extern __shared__ float sm[];
    float* Km   = sm;               // [192][192]
    float* Ssub = sm + 36864;       // [64][68]
    float* Tsub = Ssub + 4352;      // 2 x [64][68]
    float* sqs  = Tsub + 8704;      // [192]
    float* sqt  = sqs + 192;        // [192]
    float* uu   = sqt + 192;        // [192]
    float* vv   = uu + 192;         // [192]
    float* vp   = vv + 192;         // [192]
    float* red  = vp + 192;         // [512]

    int p = g_order[blockIdx.x];
    int tid = threadIdx.x;
    int n = ls[p], m = lt[p], q = 192 - n;
    int offs = g_offs[p], offt = g_offt[p];
    const float* EB = g_EMB;

    for (int i = tid; i < n; i += 512) {
        const float4* r = (const float4*)(EB + (size_t)(offs + i) * 64);
        float s = 0.f;
        #pragma unroll
        for (int k = 0; k < 16; k++) { float4 x = r[k]; s += x.x*x.x + x.y*x.y + x.z*x.z + x.w*x.w; }
        sqs[i] = s;
    }
    for (int j = tid; j < n; j += 512) {
        const float4* r = (j < m) ? (const float4*)(EB + (size_t)(Ns + offt + j) * 64)
                                  : (const float4*)g_virt;
        float s = 0.f;
        #pragma unroll
        for (int k = 0; k < 16; k++) { float4 x = r[k]; s += x.x*x.x + x.y*x.y + x.z*x.z + x.w*x.w; }
        sqt[j] = s;
    }
    for (int i = tid; i < 192; i += 512) {
        uu[i] = 1.0f / 192.0f;
        vv[i] = (i >= n && q > 0) ? (192.0f / (float)q) : 0.f;
    }

    // cost/K for real tiles only (two 64x64 tiles concurrently, one per 256-thread group)
    int g = tid >> 8, lt5 = tid & 255;
    int ti = lt5 >> 4, tj = lt5 & 15;
    float* Tg = Tsub + g * 4352;
    int ntile = (n + 63) >> 6;

    for (int it_i = 0; it_i < ntile; it_i++) {
        int i0 = it_i << 6;
        __syncthreads();
        for (int idx = tid; idx < 4096; idx += 512) {
            int nd = idx >> 6, k = idx & 63;
            int i = i0 + nd; if (i >= n) i = n - 1;
            Ssub[k * 68 + nd] = EB[(size_t)(offs + i) * 64 + k];
        }
        for (int jj = 0; jj < ntile; jj += 2) {
            int jt = jj + g;
            bool mine = (jt < ntile);
            int j0 = jt << 6;
            __syncthreads();
            if (mine) {
                for (int idx = lt5; idx < 4096; idx += 256) {
                    int nd = idx >> 6, k = idx & 63;
                    int j = j0 + nd;
                    const float* r = (j < m) ? (EB + (size_t)(Ns + offt + j) * 64) : g_virt;
                    Tg[k * 68 + nd] = r[k];
                }
            }
            __syncthreads();
            if (mine) {
                float acc[4][4] = {{0,0,0,0},{0,0,0,0},{0,0,0,0},{0,0,0,0}};
                #pragma unroll 4
                for (int k = 0; k < 64; k++) {
                    float4 a = *(const float4*)&Ssub[k * 68 + 4 * ti];
                    float4 b = *(const float4*)&Tg[k * 68 + 4 * tj];
                    acc[0][0] += a.x*b.x; acc[0][1] += a.x*b.y; acc[0][2] += a.x*b.z; acc[0][3] += a.x*b.w;
                    acc[1][0] += a.y*b.x; acc[1][1] += a.y*b.y; acc[1][2] += a.y*b.z; acc[1][3] += a.y*b.w;
                    acc[2][0] += a.z*b.x; acc[2][1] += a.z*b.y; acc[2][2] += a.z*b.z; acc[2][3] += a.z*b.w;
                    acc[3][0] += a.w*b.x; acc[3][1] += a.w*b.y; acc[3][2] += a.w*b.z; acc[3][3] += a.w*b.w;
                }
                #pragma unroll
                for (int r = 0; r < 4; r++) {
                    int i = i0 + 4 * ti + r;
                    float kv[4];
                    #pragma unroll
                    for (int c = 0; c < 4; c++) {
                        int j = j0 + 4 * tj + c;
                        if (i < n && j < n) {
                            float d = fmaxf(sqs[i] + sqt[j] - 2.0f * acc[r][c], 1e-12f);
                            float cd = d * rsqrtf(d);
                            kv[c] = __expf(-10.0f * cd);
                        } else {
                            kv[c] = ((i >= n) && (j >= n)) ? 1.f : 0.f;
                        }
                    }
                    *(float4*)&Km[i * 192 + j0 + 4 * tj] = make_float4(kv[0], kv[1], kv[2], kv[3]);
                }
            }
        }
    }
    __syncthreads();

    // Sinkhorn on the n x n real block; pad u,v stationary; cross K = 0 exactly.
    int w = tid >> 5, lane = tid & 31;
    int nh = (n + 1) >> 1;
    for (int it = 0; it < 8; it++) {
        float slo = 0.f;
        if (tid < 192) {
            int j = tid;
            if (j < n) for (int i = 0; i < nh; i++) slo += Km[i * 192 + j] * uu[i];
        } else if (tid < 384) {
            int j = tid - 192;
            if (j < n) {
                float s = 0.f;
                for (int i = nh; i < n; i++) s += Km[i * 192 + j] * uu[i];
                vp[j] = s;
            }
        }
        __syncthreads();
        if (tid < n) vv[tid] = 1.0f / (slo + vp[tid]);
        __syncthreads();
        for (int i = w; i < n; i += 16) {
            float s = 0.f;
            for (int j = lane; j < n; j += 32) s += Km[i * 192 + j] * vv[j];
            #pragma unroll
            for (int d = 16; d; d >>= 1) s += __shfl_xor_sync(0xffffffffu, s, d);
            if (lane == 0) uu[i] = 1.0f / s;
        }
        __syncthreads();
    }

    // epilogue: gamma = u K v; cost = -0.1 ln K in-block, pattern elsewhere; geds
    float* costp = cost + (size_t)p * 36864;
    float* gamp  = gamma + (size_t)p * 36864;
    float loc = 0.f;
    for (int idx = tid; idx < 9216; idx += 512) {
        int i = idx / 48, jb = (idx - i * 48) * 4;
        float4 k4 = *(const float4*)&Km[i * 192 + jb];   // garbage outside real tiles: discarded
        float ui = uu[i];
        float kk[4] = {k4.x, k4.y, k4.z, k4.w};
        float gg[4], cc[4];
        #pragma unroll
        for (int c = 0; c < 4; c++) {
            int j = jb + c;
            bool inb = (i < n) && (j < n);
            bool pad = (i >= n) && (j >= n);
            float kv = inb ? kk[c] : (pad ? 1.f : 0.f);
            cc[c] = inb ? (-0.1f * __logf(kk[c])) : (pad ? 0.f : 1000.f);
            gg[c] = ui * kv * vv[j];
            loc += gg[c] * cc[c];
        }
        *(float4*)&gamp[i * 192 + jb]  = make_float4(gg[0], gg[1], gg[2], gg[3]);
        *(float4*)&costp[i * 192 + jb] = make_float4(cc[0], cc[1], cc[2], cc[3]);
    }
    red[tid] = loc;
    __syncthreads();
    #pragma unroll
    for (int s = 256; s; s >>= 1) { if (tid < s) red[tid] += red[tid + s]; __syncthreads(); }
    if (tid == 0) geds2[p] = red[0] / (float)(n + m);
}

extern "C" void kernel_launch(void* const* d_in, const int* in_sizes, int n_in,
                              void* d_out, int out_size) {
    const float* x_s     = (const float*)d_in[0];
    const float* x_t     = (const float*)d_in[1];
    const float* W_rel0  = (const float*)d_in[2];
    const float* b_rel0  = (const float*)d_in[3];
    const float* W_root0 = (const float*)d_in[4];
    const float* W_rel1  = (const float*)d_in[5];
    const float* b_rel1  = (const float*)d_in[6];
    const float* W_root1 = (const float*)d_in[7];
    const float* W_e     = (const float*)d_in[8];
    const float* b_e     = (const float*)d_in[9];
    const float* virt    = (const float*)d_in[10];
    const int* ei_s      = (const int*)d_in[11];
    const int* ei_t      = (const int*)d_in[12];
    const int* len_s     = (const int*)d_in[13];
    const int* len_t     = (const int*)d_in[14];

    int Ns = in_sizes[0] / 32, Nt = in_sizes[1] / 32;
    int Es = in_sizes[11] / 2, Et = in_sizes[12] / 2;
    int Ntot = Ns + Nt;
    int Etot = Es + Et;

    float* out   = (float*)d_out;
    float* gamma = out;
    float* cost  = out + (size_t)PTOT * 36864;
    float* geds2 = cost + (size_t)PTOT * 36864;

    cudaFuncSetAttribute(k_gnn12, cudaFuncAttributeMaxDynamicSharedMemorySize, 17152 * 4);
    cudaFuncSetAttribute(k_pair,  cudaFuncAttributeMaxDynamicSharedMemorySize, 51392 * 4);

    int NB = (Ntot + 1023) / 1024;
    k_all<<<NB, 1024>>>(x_s, x_t, Ns * 32, Ntot * 32, len_s, len_t, virt,
                        ei_s, Es, ei_t, Et, Ns, Ntot, NB, Etot);

    int gb = (Ntot + 63) / 64;
    k_gnn0<<<gb, 256>>>(W_rel0, W_root0, b_rel0, Ntot);
    k_gnn12<<<gb, 256, 17152 * 4>>>(W_rel1, W_root1, b_rel1, W_e, b_e, Ntot);

    k_pair<<<PTOT, 512, 51392 * 4>>>(len_s, len_t, Ns, gamma, cost, geds2);
}